// round 12
// baseline (speedup 1.0000x reference)
#include <cuda_runtime.h>

#define BB   32
#define CIN  64
#define OCH  128
#define HH   64
#define WW   64
#define PP   (HH*WW)
#define OH   32
#define OW   32
#define SLICE ((size_t)BB*OCH*OH*OW)

typedef unsigned long long u64;
typedef unsigned int u32;
typedef unsigned short ush;

// ---------------- scratch (device globals) ----------------
__device__ float g_l1  [BB*OCH*HH*WW];
__device__ float g_l2  [BB*OCH*HH*WW];
__device__ float g_l3  [BB*OCH*HH*WW];
__device__ float g_prev[BB*OCH*HH*WW];
__device__ float g_aux [BB*OCH*OH*OW];
__device__ float g_attn[BB*PP];
// HWC bf16 hi/lo activation buffers
__device__ ush g_x1h[BB*PP*64],  g_x1l[BB*PP*64];     // out1
__device__ ush g_x2h[BB*PP*128], g_x2l[BB*PP*128];    // l1
__device__ ush g_x3h[BB*PP*128], g_x3l[BB*PP*128];    // l2
__device__ ush g_xph[BB*PP*128], g_xpl[BB*PP*128];    // concat(out2,out3)
// weight B-tiles: [tap][cib][128 oc][64 ci]
__device__ ush g_w1h[9*1*128*64], g_w1l[9*1*128*64];
__device__ ush g_w2h[9*2*128*64], g_w2l[9*2*128*64];
__device__ ush g_w3h[9*2*128*64], g_w3l[9*2*128*64];
__device__ ush g_wph[9*2*128*64], g_wpl[9*2*128*64];

__device__ __forceinline__ float lrelu(float x) { return x >= 0.f ? x : 0.1f * x; }

// ---- f32x2 helpers (scalar s2 path) ----
__device__ __forceinline__ u64 pk2(float lo, float hi) {
    u64 r; asm("mov.b64 %0,{%1,%2};" : "=l"(r) : "f"(lo), "f"(hi)); return r;
}
__device__ __forceinline__ u64 splat(float v) { return pk2(v, v); }
__device__ __forceinline__ void fma2(u64& d, u64 a, u64 b) {
    asm("fma.rn.f32x2 %0,%1,%2,%0;" : "+l"(d) : "l"(a), "l"(b));
}
__device__ __forceinline__ float2 unpk(u64 v) {
    float2 r; asm("mov.b64 {%0,%1},%2;" : "=f"(r.x), "=f"(r.y) : "l"(v)); return r;
}

// ---- bf16 split ----
__device__ __forceinline__ u32 bf16rn(float x) {
    u32 u = __float_as_uint(x);
    return (u + 0x7FFFu + ((u >> 16) & 1u)) >> 16;
}
__device__ __forceinline__ void bsplit(float x, ush& h, ush& l) {
    u32 uh = bf16rn(x); h = (ush)uh;
    float fh = __uint_as_float(uh << 16);
    l = (ush)bf16rn(x - fh);
}

__device__ __forceinline__ u32 smem_u32(const void* p) {
    u32 a; asm("{ .reg .u64 t; cvta.to.shared.u64 t, %1; cvt.u32.u64 %0, t; }" : "=r"(a) : "l"(p));
    return a;
}
// ldmatrix x4 (sm_75+ baseline PTX)
__device__ __forceinline__ void ldm4(u32* r, u32 a) {
    asm volatile("ldmatrix.sync.aligned.m8n8.x4.shared.b16 {%0,%1,%2,%3}, [%4];"
        : "=r"(r[0]), "=r"(r[1]), "=r"(r[2]), "=r"(r[3]) : "r"(a));
}
// mma.sync bf16 (sm_80+ baseline PTX) -> HMMA on Blackwell
__device__ __forceinline__ void mma16816(float* c, const u32* a, u32 b0, u32 b1) {
    asm volatile("mma.sync.aligned.m16n8k16.row.col.f32.bf16.bf16.f32 "
        "{%0,%1,%2,%3}, {%4,%5,%6,%7}, {%8,%9}, {%0,%1,%2,%3};"
        : "+f"(c[0]), "+f"(c[1]), "+f"(c[2]), "+f"(c[3])
        : "r"(a[0]), "r"(a[1]), "r"(a[2]), "r"(a[3]), "r"(b0), "r"(b1));
}

// ---------------------------------------------------------------------------
// Prep: NCHW fp32 (optionally concat of two) -> HWC bf16 hi/lo
// ---------------------------------------------------------------------------
template<int CI>
__global__ __launch_bounds__(256)
void asplit(const float* __restrict__ s0, const float* __restrict__ s1, int csplit,
            ush* __restrict__ oh, ush* __restrict__ ol)
{
    __shared__ float t[CI][65];
    const int b = blockIdx.y, p0 = blockIdx.x * 64;
    for (int f = threadIdx.x; f < CI * 16; f += 256) {
        int ci = f >> 4, c4 = (f & 15) * 4;
        const float* src = (ci < csplit)
            ? s0 + ((size_t)b * csplit + ci) * PP
            : s1 + ((size_t)b * (CI - csplit) + ci - csplit) * PP;
        float4 v = *(const float4*)(src + p0 + c4);
        t[ci][c4] = v.x; t[ci][c4+1] = v.y; t[ci][c4+2] = v.z; t[ci][c4+3] = v.w;
    }
    __syncthreads();
    for (int cid = threadIdx.x; cid < 64 * (CI / 8); cid += 256) {
        int px = cid / (CI / 8), k8 = cid % (CI / 8);
        u32 hu[4], lu[4];
#pragma unroll
        for (int j = 0; j < 4; j++) {
            ush h0, l0, h1, l1;
            bsplit(t[k8*8 + 2*j][px],     h0, l0);
            bsplit(t[k8*8 + 2*j + 1][px], h1, l1);
            hu[j] = (u32)h0 | ((u32)h1 << 16);
            lu[j] = (u32)l0 | ((u32)l1 << 16);
        }
        size_t off = ((size_t)b * PP + p0 + px) * CI + k8 * 8;
        *(uint4*)(oh + off) = *(uint4*)hu;
        *(uint4*)(ol + off) = *(uint4*)lu;
    }
}

// Prep: weights [128][CI][3][3] fp32 -> [tap][cib][128][64] bf16 hi/lo
__global__ void wsplit(const float* __restrict__ w, int CI,
                       ush* __restrict__ oh, ush* __restrict__ ol)
{
    int i = blockIdx.x * 256 + threadIdx.x;
    if (i >= 128 * CI * 9) return;
    int oc = i / (CI * 9), r = i % (CI * 9), ci = r / 9, tap = r % 9;
    ush h, l; bsplit(w[i], h, l);
    size_t o = (((size_t)(tap * (CI >> 6) + (ci >> 6)) * 128 + oc) * 64 + (ci & 63));
    oh[o] = h; ol[o] = l;
}

// ---------------------------------------------------------------------------
// Tensor-core stride-1 3x3 conv via mma.sync bf16 hi/lo (HMMA path).
// CTA: 256 thr (8 warps, 2x4), D = 128 px x 128 oc in registers.
// A (activations) double-buffered in smem w/ 16B XOR swizzle -> ldmatrix.
// B (weights) direct per-thread LDG.32 (L2-hot, shared across CTAs).
// Grid (32 px-tiles, 1, 32 batch).
// ---------------------------------------------------------------------------
template<int CIB>
__global__ __launch_bounds__(256, 2)
void mconv(const ush* __restrict__ ah, const ush* __restrict__ al,
           const ush* __restrict__ wh, const ush* __restrict__ wl,
           const float* __restrict__ bias, float* __restrict__ outw,
           ush* __restrict__ xoh, ush* __restrict__ xol)
{
    constexpr int CI = CIB * 64;
    constexpr int S  = 9 * CIB * 4;           // K16 steps
    __shared__ __align__(16) ush sA[2][2][128][16];   // [buf][hi/lo][px][ci16]
    __shared__ float sbias[128];

    const int tid  = threadIdx.x;
    const int lane = tid & 31, wid = tid >> 5;
    const int wm = wid >> 2, wn = wid & 3;    // warp tile coords (2 x 4)
    const int b = blockIdx.z, y0 = blockIdx.x * 2;

    if (tid < 128) sbias[tid] = bias[tid];

    // staging mapping: thread -> (pixel, 8-ci chunk)
    const int spx = tid >> 1, sc8 = (tid & 1) * 8;
    const int sry = spx >> 6, sx = spx & 63;
    const u32 sbA = smem_u32(&sA[0][0][0][0]);

    float acc[4][4][4];
#pragma unroll
    for (int mt = 0; mt < 4; mt++)
#pragma unroll
        for (int nt = 0; nt < 4; nt++)
#pragma unroll
            for (int r = 0; r < 4; r++) acc[mt][nt][r] = 0.f;

    const uint4 z4 = make_uint4(0, 0, 0, 0);
    uint4 vh, vl;

    auto ldgA = [&](int s) {
        int tap = s / (4 * CIB), kc = s - tap * (4 * CIB);
        int ky = tap / 3, kx = tap - ky * 3;
        int yy = y0 + sry + ky - 1, xx = sx + kx - 1;
        bool ok = ((unsigned)yy < HH) & ((unsigned)xx < WW);
        size_t off = ((size_t)b * PP + yy * WW + xx) * (size_t)CI + kc * 16 + sc8;
        vh = ok ? *(const uint4*)(ah + off) : z4;
        vl = ok ? *(const uint4*)(al + off) : z4;
    };
    auto stsA = [&](int buf) {
        int ch = (sc8 >> 3) ^ (spx & 1);      // XOR swizzle of 16B chunks
        *(uint4*)((char*)&sA[buf][0][0][0] + spx * 32 + ch * 16) = vh;
        *(uint4*)((char*)&sA[buf][1][0][0] + spx * 32 + ch * 16) = vl;
    };

    ldgA(0); stsA(0); __syncthreads();

    for (int s = 0; s < S; s++) {
        const int buf = s & 1;
        if (s + 1 < S) ldgA(s + 1);

        // B fragments: thread holds w[oc][k..k+1] and w[oc][k+8..k+9]
        const int tap = s / (4 * CIB), kc = s - tap * (4 * CIB);
        u32 bh[4][2], bl[4][2];
        {
            const int oc0 = wn * 32 + (lane >> 2);
            const size_t wbase =
                ((size_t)(tap * CIB + (kc >> 2)) * 128 + oc0) * 64 + (kc & 3) * 16 + (lane & 3) * 2;
#pragma unroll
            for (int nt = 0; nt < 4; nt++) {
                const size_t wo = wbase + (size_t)nt * 8 * 64;
                bh[nt][0] = *(const u32*)(wh + wo);
                bh[nt][1] = *(const u32*)(wh + wo + 8);
                bl[nt][0] = *(const u32*)(wl + wo);
                bl[nt][1] = *(const u32*)(wl + wo + 8);
            }
        }

#pragma unroll
        for (int mt = 0; mt < 4; mt++) {
            const int row = wm * 64 + mt * 16 + (lane & 15);
            const int ch  = (lane >> 4) ^ (row & 1);
            const u32 ao  = sbA + buf * 8192 + row * 32 + ch * 16;
            u32 ahr[4], alr[4];
            ldm4(ahr, ao);
            ldm4(alr, ao + 4096);
#pragma unroll
            for (int nt = 0; nt < 4; nt++) {
                mma16816(acc[mt][nt], ahr, bh[nt][0], bh[nt][1]);   // hi*hi
                mma16816(acc[mt][nt], ahr, bl[nt][0], bl[nt][1]);   // hi*lo
                mma16816(acc[mt][nt], alr, bh[nt][0], bh[nt][1]);   // lo*hi
            }
        }

        if (s + 1 < S) stsA((s + 1) & 1);
        __syncthreads();
    }

    // epilogue: bias + lrelu, NCHW fp32 write, optional HWC bf16 hi/lo write
    const int r0 = lane >> 2, cp = (lane & 3) * 2;
#pragma unroll
    for (int mt = 0; mt < 4; mt++) {
#pragma unroll
        for (int half = 0; half < 2; half++) {
            const int px = wm * 64 + mt * 16 + r0 + half * 8;
            const int y = y0 + (px >> 6), x = px & 63;
            const size_t nb = (((size_t)b * OCH) * HH + y) * WW + x;
            const size_t hb = ((size_t)b * PP + y * WW + x) * 128;
#pragma unroll
            for (int nt = 0; nt < 4; nt++) {
                const int oc = wn * 32 + nt * 8 + cp;
                const float f0 = lrelu(acc[mt][nt][half * 2 + 0] + sbias[oc]);
                const float f1 = lrelu(acc[mt][nt][half * 2 + 1] + sbias[oc + 1]);
                outw[nb + (size_t)oc * PP]       = f0;
                outw[nb + (size_t)(oc + 1) * PP] = f1;
                if (xoh) {
                    ush h0, l0, h1, l1;
                    bsplit(f0, h0, l0); bsplit(f1, h1, l1);
                    *(u32*)(xoh + hb + oc) = (u32)h0 | ((u32)h1 << 16);
                    *(u32*)(xol + hb + oc) = (u32)l0 | ((u32)l1 << 16);
                }
            }
        }
    }
}

// ---------------------------------------------------------------------------
// Attention softmax (unchanged)
// ---------------------------------------------------------------------------
__global__ void attn_kernel(const float* __restrict__ out1,
                            const float* __restrict__ lin_w,
                            const float* __restrict__ lin_b,
                            float* __restrict__ attn)
{
    const int b = blockIdx.x, tid = threadIdx.x;
    const float* xb = out1 + (size_t)b * CIN * PP;
    float logit[16], lmax = -1e30f;
#pragma unroll
    for (int i = 0; i < 16; i++) {
        const int p = tid + i * 256;
        float acc = lin_b[p];
        const float4* wr = (const float4*)(lin_w + (size_t)p * CIN);
#pragma unroll
        for (int c4 = 0; c4 < CIN / 4; c4++) {
            float4 w4 = wr[c4];
            acc = fmaf(w4.x, xb[(c4*4+0)*PP + p], acc);
            acc = fmaf(w4.y, xb[(c4*4+1)*PP + p], acc);
            acc = fmaf(w4.z, xb[(c4*4+2)*PP + p], acc);
            acc = fmaf(w4.w, xb[(c4*4+3)*PP + p], acc);
        }
        logit[i] = acc; lmax = fmaxf(lmax, acc);
    }
    __shared__ float red[256];
    red[tid] = lmax; __syncthreads();
    for (int s = 128; s > 0; s >>= 1) { if (tid < s) red[tid] = fmaxf(red[tid], red[tid+s]); __syncthreads(); }
    const float m = red[0]; __syncthreads();
    float lsum = 0.f;
#pragma unroll
    for (int i = 0; i < 16; i++) { logit[i] = expf(logit[i] - m); lsum += logit[i]; }
    red[tid] = lsum; __syncthreads();
    for (int s = 128; s > 0; s >>= 1) { if (tid < s) red[tid] += red[tid+s]; __syncthreads(); }
    const float inv = 1.0f / red[0];
#pragma unroll
    for (int i = 0; i < 16; i++) attn[(size_t)b * PP + tid + i*256] = logit[i] * inv;
}

// ---------------------------------------------------------------------------
// Scalar stride-2 conv (unchanged, proven)
// ---------------------------------------------------------------------------
template<int CI>
__global__ __launch_bounds__(256, 2)
void conv_s2(const float* __restrict__ in0, const float* __restrict__ in1, int csplit,
             const float* __restrict__ wgt, const float* __restrict__ bias,
             float* __restrict__ out)
{
    __shared__ __align__(16) float s_in[2][65][68];
    __shared__ __align__(16) u64   s_w[2][8][12];
    const int tid = threadIdx.x, tx = tid & 7, ty = tid >> 3;
    const int ocg = blockIdx.y, b = blockIdx.z;
    const int warp = tid >> 5, lane = tid & 31;
    const int woc = tid / 9, wkk = tid - woc * 9;
    const int wk = wkk / 3, wt = wkk - wk * 3;
    const bool wme = tid < 144;
    u64 acc2[8][4];
#pragma unroll
    for (int o = 0; o < 8; o++)
#pragma unroll
        for (int j = 0; j < 4; j++) acc2[o][j] = 0ULL;
    float pfA[9], pfB[9], pfE[9], wv = 0.f;
    auto load_chunk = [&](int cg) {
        const float* src = (cg < csplit)
            ? in0 + ((size_t)b * csplit + cg) * PP
            : in1 + ((size_t)b * (CI - csplit) + (cg - csplit)) * PP;
#pragma unroll
        for (int k = 0; k < 9; k++) {
            const int iy = warp + 8*k, gy = iy - 1;
            const bool rowok = (iy < 65) & ((unsigned)gy < HH);
            const float* rowp = src + gy * WW;
            pfA[k] = (rowok && (unsigned)(lane-1) < WW) ? rowp[lane-1] : 0.f;
            pfB[k] = (rowok && lane + 31 < WW) ? rowp[lane+31] : 0.f;
            pfE[k] = (rowok && lane == 0) ? rowp[63] : 0.f;
        }
        if (wme) wv = wgt[((size_t)(ocg*16 + woc) * CI + cg) * 9 + wkk];
    };
    auto store_chunk = [&](int bf) {
#pragma unroll
        for (int k = 0; k < 9; k++) {
            const int iy = warp + 8*k;
            if (k < 8 || iy < 65) {
                float* srow = &s_in[bf][iy][0];
                srow[lane] = pfA[k]; srow[lane+32] = pfB[k];
                if (lane == 0) srow[64] = pfE[k];
            }
        }
        if (wme) ((float*)&s_w[bf][woc >> 1][wk*4 + wt])[woc & 1] = wv;
    };
    load_chunk(0); store_chunk(0); __syncthreads();
    for (int c = 0; c < CI; c++) {
        const int bf = c & 1;
        if (c + 1 < CI) load_chunk(c + 1);
#pragma unroll
        for (int k = 0; k < 3; k++) {
            const float4* rp = (const float4*)&s_in[bf][2*ty + k][8*tx];
            const float4 ra = rp[0], rb = rp[1], rc = rp[2];
            u64 rs[9];
            rs[0]=splat(ra.x); rs[1]=splat(ra.y); rs[2]=splat(ra.z); rs[3]=splat(ra.w);
            rs[4]=splat(rb.x); rs[5]=splat(rb.y); rs[6]=splat(rb.z); rs[7]=splat(rb.w);
            rs[8]=splat(rc.x);
#pragma unroll
            for (int o2 = 0; o2 < 8; o2++) {
                const ulonglong2 w01 = *(const ulonglong2*)&s_w[bf][o2][k*4];
                const u64 w2 = s_w[bf][o2][k*4 + 2];
#pragma unroll
                for (int j = 0; j < 4; j++) {
                    fma2(acc2[o2][j], rs[2*j],     w01.x);
                    fma2(acc2[o2][j], rs[2*j + 1], w01.y);
                    fma2(acc2[o2][j], rs[2*j + 2], w2);
                }
            }
        }
        if (c + 1 < CI) store_chunk(bf ^ 1);
        __syncthreads();
    }
#pragma unroll
    for (int o2 = 0; o2 < 8; o2++) {
        const float b0 = bias[ocg*16 + 2*o2], b1 = bias[ocg*16 + 2*o2 + 1];
        float r0[4], r1[4];
#pragma unroll
        for (int j = 0; j < 4; j++) {
            float2 v = unpk(acc2[o2][j]);
            r0[j] = lrelu(v.x + b0); r1[j] = lrelu(v.y + b1);
        }
        size_t oo0 = (((size_t)b * OCH + ocg*16 + 2*o2)     * OH + ty) * OW + tx*4;
        size_t oo1 = (((size_t)b * OCH + ocg*16 + 2*o2 + 1) * OH + ty) * OW + tx*4;
        *(float4*)(out + oo0) = make_float4(r0[0], r0[1], r0[2], r0[3]);
        *(float4*)(out + oo1) = make_float4(r1[0], r1[1], r1[2], r1[3]);
    }
}

// ---------------------------------------------------------------------------
__global__ void bo3_kernel(const float* __restrict__ prev,
                           const float* __restrict__ attn,
                           float* __restrict__ out)
{
    const int idx = blockIdx.x * 256 + threadIdx.x;
    const int ox = idx & 31, oy = (idx >> 5) & 31, bc = idx >> 10;
    const int b = bc >> 7;
    const float* pv = prev + (size_t)bc * PP;
    const float* at = attn + (size_t)b * PP;
    const float BIN = 63.0f / 32.0f;
    float acc = 0.f;
#pragma unroll
    for (int sy = 0; sy < 2; sy++) {
        const float ys = ((float)oy + 0.25f + 0.5f * sy) * BIN;
        const int y0 = (int)ys, y1 = min(y0 + 1, HH - 1);
        const float ly = ys - (float)y0, hy = 1.f - ly;
#pragma unroll
        for (int sx = 0; sx < 2; sx++) {
            const float xs = ((float)ox + 0.25f + 0.5f * sx) * BIN;
            const int x0 = (int)xs, x1 = min(x0 + 1, WW - 1);
            const float lx = xs - (float)x0, hx = 1.f - lx;
            const float f00 = pv[y0*WW+x0]*at[y0*WW+x0], f01 = pv[y0*WW+x1]*at[y0*WW+x1];
            const float f10 = pv[y1*WW+x0]*at[y1*WW+x0], f11 = pv[y1*WW+x1]*at[y1*WW+x1];
            acc += hy * (hx*f00 + lx*f01) + ly * (hx*f10 + lx*f11);
        }
    }
    out[idx] = acc * 0.25f;
}

__global__ void combine_kernel(const float* __restrict__ l2,
                               const float* __restrict__ aux,
                               float* __restrict__ out)
{
    const int idx = blockIdx.x * 256 + threadIdx.x;
    const int ox = idx & 31, oy = (idx >> 5) & 31, bc = idx >> 10;
    const float* src = l2 + (size_t)bc * PP;
    const float BIN = 63.0f / 32.0f;
    float acc = 0.f;
#pragma unroll
    for (int sy = 0; sy < 2; sy++) {
        const float ys = ((float)oy + 0.25f + 0.5f * sy) * BIN;
        const int y0 = (int)ys, y1 = min(y0 + 1, HH - 1);
        const float ly = ys - (float)y0, hy = 1.f - ly;
#pragma unroll
        for (int sx = 0; sx < 2; sx++) {
            const float xs = ((float)ox + 0.25f + 0.5f * sx) * BIN;
            const int x0 = (int)xs, x1 = min(x0 + 1, WW - 1);
            const float lx = xs - (float)x0, hx = 1.f - lx;
            acc += hy * (hx*src[y0*WW+x0] + lx*src[y0*WW+x1])
                 + ly * (hx*src[y1*WW+x0] + lx*src[y1*WW+x1]);
        }
    }
    out[idx] = acc * 0.25f + aux[idx] + out[SLICE + idx] + out[2*SLICE + idx];
}

// ---------------------------------------------------------------------------
extern "C" void kernel_launch(void* const* d_in, const int* in_sizes, int n_in,
                              void* d_out, int out_size)
{
    const float* out1   = (const float*)d_in[0];
    const float* out2   = (const float*)d_in[1];
    const float* out3   = (const float*)d_in[2];
    const float* w1     = (const float*)d_in[3];
    const float* b1     = (const float*)d_in[4];
    const float* w2     = (const float*)d_in[5];
    const float* b2     = (const float*)d_in[6];
    const float* w3     = (const float*)d_in[7];
    const float* b3     = (const float*)d_in[8];
    const float* w_aux  = (const float*)d_in[9];
    const float* b_aux  = (const float*)d_in[10];
    const float* w_b2   = (const float*)d_in[11];
    const float* b_b2   = (const float*)d_in[12];
    const float* w_prev = (const float*)d_in[13];
    const float* b_prev = (const float*)d_in[14];
    const float* lin_w  = (const float*)d_in[15];
    const float* lin_b  = (const float*)d_in[16];
    float* out = (float*)d_out;

    float *l1, *l2, *l3, *prev, *aux, *attn;
    cudaGetSymbolAddress((void**)&l1,   g_l1);
    cudaGetSymbolAddress((void**)&l2,   g_l2);
    cudaGetSymbolAddress((void**)&l3,   g_l3);
    cudaGetSymbolAddress((void**)&prev, g_prev);
    cudaGetSymbolAddress((void**)&aux,  g_aux);
    cudaGetSymbolAddress((void**)&attn, g_attn);
    ush *x1h,*x1l,*x2h,*x2l,*x3h,*x3l,*xph,*xpl;
    ush *w1h,*w1l,*w2h,*w2l,*w3h,*w3l,*wph,*wpl;
    cudaGetSymbolAddress((void**)&x1h, g_x1h); cudaGetSymbolAddress((void**)&x1l, g_x1l);
    cudaGetSymbolAddress((void**)&x2h, g_x2h); cudaGetSymbolAddress((void**)&x2l, g_x2l);
    cudaGetSymbolAddress((void**)&x3h, g_x3h); cudaGetSymbolAddress((void**)&x3l, g_x3l);
    cudaGetSymbolAddress((void**)&xph, g_xph); cudaGetSymbolAddress((void**)&xpl, g_xpl);
    cudaGetSymbolAddress((void**)&w1h, g_w1h); cudaGetSymbolAddress((void**)&w1l, g_w1l);
    cudaGetSymbolAddress((void**)&w2h, g_w2h); cudaGetSymbolAddress((void**)&w2l, g_w2l);
    cudaGetSymbolAddress((void**)&w3h, g_w3h); cudaGetSymbolAddress((void**)&w3l, g_w3l);
    cudaGetSymbolAddress((void**)&wph, g_wph); cudaGetSymbolAddress((void**)&wpl, g_wpl);

    static cudaStream_t sB = nullptr, sC = nullptr;
    static cudaEvent_t eFork = nullptr, eL2 = nullptr, eB = nullptr, eC = nullptr;
    if (!sB) {
        cudaStreamCreateWithFlags(&sB, cudaStreamNonBlocking);
        cudaStreamCreateWithFlags(&sC, cudaStreamNonBlocking);
        cudaEventCreateWithFlags(&eFork, cudaEventDisableTiming);
        cudaEventCreateWithFlags(&eL2,   cudaEventDisableTiming);
        cudaEventCreateWithFlags(&eB,    cudaEventDisableTiming);
        cudaEventCreateWithFlags(&eC,    cudaEventDisableTiming);
    }

    const dim3 gsM(32, 1, 32);       // tensor convs
    const dim3 gsA(64, 32);          // asplit
    const dim3 gs2(1, OCH/16, BB);   // stride-2 convs
    const int  nPix = (int)(SLICE / 256);

    cudaEventRecord(eFork, 0);
    cudaStreamWaitEvent(sB, eFork, 0);

    // ---- stream B: attn + prev chain + bo3 ----
    attn_kernel<<<BB, 256, 0, sB>>>(out1, lin_w, lin_b, attn);
    wsplit<<<(128*128*9 + 255)/256, 256, 0, sB>>>(w_prev, 128, wph, wpl);
    asplit<128><<<gsA, 256, 0, sB>>>(out2, out3, 64, xph, xpl);
    mconv<2><<<gsM, 256, 0, sB>>>(xph, xpl, wph, wpl, b_prev, prev, nullptr, nullptr);
    bo3_kernel<<<nPix, 256, 0, sB>>>(prev, attn, out + 2*SLICE);
    cudaEventRecord(eB, sB);

    // ---- main chain ----
    wsplit<<<(128*64*9  + 255)/256, 256>>>(w1, 64,  w1h, w1l);
    wsplit<<<(128*128*9 + 255)/256, 256>>>(w2, 128, w2h, w2l);
    wsplit<<<(128*128*9 + 255)/256, 256>>>(w3, 128, w3h, w3l);
    asplit<64><<<gsA, 256>>>(out1, nullptr, 64, x1h, x1l);
    mconv<1><<<gsM, 256>>>(x1h, x1l, w1h, w1l, b1, l1, x2h, x2l);
    mconv<2><<<gsM, 256>>>(x2h, x2l, w2h, w2l, b2, l2, x3h, x3l);

    // fork C: conv_b2 needs only l1,l2 (NCHW fp32)
    cudaEventRecord(eL2, 0);
    cudaStreamWaitEvent(sC, eL2, 0);
    conv_s2<256><<<gs2, 256, 0, sC>>>(l1, l2, 128, w_b2, b_b2, out + SLICE);
    cudaEventRecord(eC, sC);

    mconv<2><<<gsM, 256>>>(x3h, x3l, w3h, w3l, b3, l3, nullptr, nullptr);
    conv_s2<128><<<gs2, 256>>>(l3, nullptr, 128, w_aux, b_aux, aux);

    cudaStreamWaitEvent(0, eB, 0);
    cudaStreamWaitEvent(0, eC, 0);
    combine_kernel<<<nPix, 256>>>(l2, aux, out);
}

// round 13
// speedup vs baseline: 2.6842x; 2.6842x over previous
#include <cuda_runtime.h>

#define BB   32
#define CIN  64
#define OCH  128
#define HH   64
#define WW   64
#define PP   (HH*WW)
#define OH   32
#define OW   32
#define SLICE ((size_t)BB*OCH*OH*OW)

typedef unsigned long long u64;
typedef unsigned int u32;
typedef unsigned short ush;

// ---------------- scratch (device globals) ----------------
__device__ float g_l2  [BB*OCH*HH*WW];
__device__ float g_prev[BB*OCH*HH*WW];
__device__ float g_aux [BB*OCH*OH*OW];
__device__ float g_attn[BB*PP];
// HWC bf16 hi/lo activation buffers
__device__ ush g_x1h[BB*PP*64],  g_x1l[BB*PP*64];     // out1
__device__ ush g_x2h[BB*PP*128], g_x2l[BB*PP*128];    // l1
__device__ ush g_x3h[BB*PP*128], g_x3l[BB*PP*128];    // l2
__device__ ush g_x4h[BB*PP*128], g_x4l[BB*PP*128];    // l3
__device__ ush g_xph[BB*PP*128], g_xpl[BB*PP*128];    // concat(out2,out3)
// weight B-tiles: [tap][cib][128 oc][64 ci]
__device__ ush g_w1h[9*1*128*64], g_w1l[9*1*128*64];
__device__ ush g_w2h[9*2*128*64], g_w2l[9*2*128*64];
__device__ ush g_w3h[9*2*128*64], g_w3l[9*2*128*64];
__device__ ush g_wph[9*2*128*64], g_wpl[9*2*128*64];
__device__ ush g_wbh[9*4*128*64], g_wbl[9*4*128*64];  // w_b2 (CI=256)
__device__ ush g_wah[9*2*128*64], g_wal[9*2*128*64];  // w_aux

__device__ __forceinline__ float lrelu(float x) { return x >= 0.f ? x : 0.1f * x; }

// ---- bf16 split ----
__device__ __forceinline__ u32 bf16rn(float x) {
    u32 u = __float_as_uint(x);
    return (u + 0x7FFFu + ((u >> 16) & 1u)) >> 16;
}
__device__ __forceinline__ void bsplit(float x, ush& h, ush& l) {
    u32 uh = bf16rn(x); h = (ush)uh;
    float fh = __uint_as_float(uh << 16);
    l = (ush)bf16rn(x - fh);
}

__device__ __forceinline__ u32 smem_u32(const void* p) {
    u32 a; asm("{ .reg .u64 t; cvta.to.shared.u64 t, %1; cvt.u32.u64 %0, t; }" : "=r"(a) : "l"(p));
    return a;
}
// ldmatrix x4 (sm_75+ baseline PTX)
__device__ __forceinline__ void ldm4(u32* r, u32 a) {
    asm volatile("ldmatrix.sync.aligned.m8n8.x4.shared.b16 {%0,%1,%2,%3}, [%4];"
        : "=r"(r[0]), "=r"(r[1]), "=r"(r[2]), "=r"(r[3]) : "r"(a));
}
// mma.sync bf16 (sm_80+ baseline PTX) -> HMMA on Blackwell
__device__ __forceinline__ void mma16816(float* c, const u32* a, u32 b0, u32 b1) {
    asm volatile("mma.sync.aligned.m16n8k16.row.col.f32.bf16.bf16.f32 "
        "{%0,%1,%2,%3}, {%4,%5,%6,%7}, {%8,%9}, {%0,%1,%2,%3};"
        : "+f"(c[0]), "+f"(c[1]), "+f"(c[2]), "+f"(c[3])
        : "r"(a[0]), "r"(a[1]), "r"(a[2]), "r"(a[3]), "r"(b0), "r"(b1));
}

// ---------------------------------------------------------------------------
// Prep: NCHW fp32 (optionally concat of two) -> HWC bf16 hi/lo
// ---------------------------------------------------------------------------
template<int CI>
__global__ __launch_bounds__(256)
void asplit(const float* __restrict__ s0, const float* __restrict__ s1, int csplit,
            ush* __restrict__ oh, ush* __restrict__ ol)
{
    __shared__ float t[CI][65];
    const int b = blockIdx.y, p0 = blockIdx.x * 64;
    for (int f = threadIdx.x; f < CI * 16; f += 256) {
        int ci = f >> 4, c4 = (f & 15) * 4;
        const float* src = (ci < csplit)
            ? s0 + ((size_t)b * csplit + ci) * PP
            : s1 + ((size_t)b * (CI - csplit) + ci - csplit) * PP;
        float4 v = *(const float4*)(src + p0 + c4);
        t[ci][c4] = v.x; t[ci][c4+1] = v.y; t[ci][c4+2] = v.z; t[ci][c4+3] = v.w;
    }
    __syncthreads();
    for (int cid = threadIdx.x; cid < 64 * (CI / 8); cid += 256) {
        int px = cid / (CI / 8), k8 = cid % (CI / 8);
        u32 hu[4], lu[4];
#pragma unroll
        for (int j = 0; j < 4; j++) {
            ush h0, l0, h1, l1;
            bsplit(t[k8*8 + 2*j][px],     h0, l0);
            bsplit(t[k8*8 + 2*j + 1][px], h1, l1);
            hu[j] = (u32)h0 | ((u32)h1 << 16);
            lu[j] = (u32)l0 | ((u32)l1 << 16);
        }
        size_t off = ((size_t)b * PP + p0 + px) * CI + k8 * 8;
        *(uint4*)(oh + off) = *(uint4*)hu;
        *(uint4*)(ol + off) = *(uint4*)lu;
    }
}

// Prep: weights [128][CI][3][3] fp32 -> [tap][cib][128][64] bf16 hi/lo
__global__ void wsplit(const float* __restrict__ w, int CI,
                       ush* __restrict__ oh, ush* __restrict__ ol)
{
    int i = blockIdx.x * 256 + threadIdx.x;
    if (i >= 128 * CI * 9) return;
    int oc = i / (CI * 9), r = i % (CI * 9), ci = r / 9, tap = r % 9;
    ush h, l; bsplit(w[i], h, l);
    size_t o = (((size_t)(tap * (CI >> 6) + (ci >> 6)) * 128 + oc) * 64 + (ci & 63));
    oh[o] = h; ol[o] = l;
}

// ---------------------------------------------------------------------------
// Tensor-core 3x3 conv (stride 1 or 2) via mma.sync bf16 hi/lo.
// CTA: 256 thr (8 warps 2x4); D = 128 out-px x 128 oc in registers.
// A and W both staged in double-buffered smem (bit-2 XOR swizzle) -> ldmatrix.
// Input may be channel-concat of two HWC buffers (split at cib1*64).
// ---------------------------------------------------------------------------
template<int CIB, int STRIDE>
__global__ __launch_bounds__(256, 2)
void mconv(const ush* __restrict__ ah, const ush* __restrict__ al,
           const ush* __restrict__ ah2, const ush* __restrict__ al2, int cib1,
           const ush* __restrict__ wh, const ush* __restrict__ wl,
           const float* __restrict__ bias, float* __restrict__ outw,
           ush* __restrict__ xoh, ush* __restrict__ xol)
{
    constexpr int S    = 9 * CIB * 4;          // K16 steps
    constexpr int OWO  = WW / STRIDE;          // out width
    constexpr int ROWS = 128 / OWO;            // out rows per tile
    constexpr int PPO  = (HH / STRIDE) * OWO;  // out pixels per channel
    __shared__ __align__(16) ush sA[2][2][128][16];   // [buf][hi/lo][px][ci16]
    __shared__ __align__(16) ush sW[2][2][128][16];   // [buf][hi/lo][oc][ci16]
    __shared__ float sbias[128];

    const int tid  = threadIdx.x;
    const int lane = tid & 31, wid = tid >> 5;
    const int wm = wid >> 2, wn = wid & 3;     // warp tile coords (2 x 4)
    const int b = blockIdx.z, y0 = blockIdx.x * ROWS;

    if (tid < 128) sbias[tid] = bias[tid];

    // staging mapping: thread -> (pixel, 8-ci chunk)
    const int spx = tid >> 1, sc8 = (tid & 1) * 8;
    const int sry = spx / OWO, sx = spx % OWO;
    const int CI1 = cib1 * 64, CI2 = CIB * 64 - CI1;
    const u32 sAb = smem_u32(&sA[0][0][0][0]);
    const u32 sWb = smem_u32(&sW[0][0][0][0]);

    float acc[4][4][4];
#pragma unroll
    for (int mt = 0; mt < 4; mt++)
#pragma unroll
        for (int nt = 0; nt < 4; nt++)
#pragma unroll
            for (int r = 0; r < 4; r++) acc[mt][nt][r] = 0.f;

    const uint4 z4 = make_uint4(0, 0, 0, 0);
    uint4 vh, vl, wvh, wvl;

    auto ldgA = [&](int s) {
        int tap = s / (4 * CIB), kc = s - tap * (4 * CIB);
        int ky = tap / 3, kx = tap - ky * 3;
        int yy = STRIDE * (y0 + sry) + ky - 1, xx = STRIDE * sx + kx - 1;
        bool ok = ((unsigned)yy < HH) & ((unsigned)xx < WW);
        int ci = kc * 16 + sc8;
        const ush *ph, *pl;
        if (ci < CI1) {
            size_t off = ((size_t)b * PP + yy * WW + xx) * (size_t)CI1 + ci;
            ph = ah + off; pl = al + off;
        } else {
            size_t off = ((size_t)b * PP + yy * WW + xx) * (size_t)CI2 + (ci - CI1);
            ph = ah2 + off; pl = al2 + off;
        }
        vh = ok ? *(const uint4*)ph : z4;
        vl = ok ? *(const uint4*)pl : z4;
    };
    auto ldgW = [&](int s) {
        int tap = s / (4 * CIB), kc = s - tap * (4 * CIB);
        size_t off = ((size_t)(tap * CIB + (kc >> 2)) * 128 + (tid >> 1)) * 64
                   + (kc & 3) * 16 + (tid & 1) * 8;
        wvh = *(const uint4*)(wh + off);
        wvl = *(const uint4*)(wl + off);
    };
    auto stsAW = [&](int buf) {
        {   // A: row spx, chunk sc8>>3, swizzle with row bit2
            int ch = (sc8 >> 3) ^ ((spx >> 2) & 1);
            char* base = (char*)&sA[buf][0][0][0] + spx * 32 + ch * 16;
            *(uint4*)base          = vh;
            *(uint4*)(base + 4096) = vl;
        }
        {   // W: row tid>>1, chunk tid&1
            int row = tid >> 1, c = tid & 1;
            int ch = c ^ ((row >> 2) & 1);
            char* base = (char*)&sW[buf][0][0][0] + row * 32 + ch * 16;
            *(uint4*)base          = wvh;
            *(uint4*)(base + 4096) = wvl;
        }
    };

    ldgA(0); ldgW(0); stsAW(0); __syncthreads();

    for (int s = 0; s < S; s++) {
        const int buf = s & 1;
        if (s + 1 < S) { ldgA(s + 1); ldgW(s + 1); }

        // ---- W fragments via ldmatrix (non-trans == mma B layout) ----
        u32 bh[4][2], bl[4][2];
        const u32 wbase = sWb + buf * 8192;
#pragma unroll
        for (int ntp = 0; ntp < 2; ntp++) {
            const int sel = lane >> 3;
            const int row = wn * 32 + ntp * 16 + ((sel & 2) << 2) + (lane & 7);
            const int ch = (sel & 1) ^ ((row >> 2) & 1);
            const u32 ad = wbase + row * 32 + ch * 16;
            u32 r[4];
            ldm4(r, ad);
            bh[ntp*2][0] = r[0]; bh[ntp*2][1] = r[1];
            bh[ntp*2+1][0] = r[2]; bh[ntp*2+1][1] = r[3];
            ldm4(r, ad + 4096);
            bl[ntp*2][0] = r[0]; bl[ntp*2][1] = r[1];
            bl[ntp*2+1][0] = r[2]; bl[ntp*2+1][1] = r[3];
        }

#pragma unroll
        for (int mt = 0; mt < 4; mt++) {
            const int row = wm * 64 + mt * 16 + (lane & 15);
            const int ch = (lane >> 4) ^ ((row >> 2) & 1);
            const u32 ao = sAb + buf * 8192 + row * 32 + ch * 16;
            u32 ahr[4], alr[4];
            ldm4(ahr, ao);
            ldm4(alr, ao + 4096);
#pragma unroll
            for (int nt = 0; nt < 4; nt++) {
                mma16816(acc[mt][nt], ahr, bh[nt][0], bh[nt][1]);   // hi*hi
                mma16816(acc[mt][nt], ahr, bl[nt][0], bl[nt][1]);   // hi*lo
                mma16816(acc[mt][nt], alr, bh[nt][0], bh[nt][1]);   // lo*hi
            }
        }

        __syncthreads();
        if (s + 1 < S) { stsAW((s + 1) & 1); __syncthreads(); }
    }

    // epilogue: bias + lrelu; optional NCHW fp32 write; optional HWC hi/lo write
    const int r0 = lane >> 2, cp = (lane & 3) * 2;
#pragma unroll
    for (int mt = 0; mt < 4; mt++) {
#pragma unroll
        for (int half = 0; half < 2; half++) {
            const int px = wm * 64 + mt * 16 + r0 + half * 8;
            const int y = y0 + px / OWO, x = px % OWO;
            const size_t nb = (((size_t)b * OCH) * (size_t)(HH / STRIDE) + y) * OWO + x;
            const size_t hb = ((size_t)b * PP + y * WW + x) * 128;
#pragma unroll
            for (int nt = 0; nt < 4; nt++) {
                const int oc = wn * 32 + nt * 8 + cp;
                const float f0 = lrelu(acc[mt][nt][half * 2 + 0] + sbias[oc]);
                const float f1 = lrelu(acc[mt][nt][half * 2 + 1] + sbias[oc + 1]);
                if (outw) {
                    outw[nb + (size_t)oc * PPO]       = f0;
                    outw[nb + (size_t)(oc + 1) * PPO] = f1;
                }
                if (xoh) {
                    ush h0, l0, h1, l1;
                    bsplit(f0, h0, l0); bsplit(f1, h1, l1);
                    *(u32*)(xoh + hb + oc) = (u32)h0 | ((u32)h1 << 16);
                    *(u32*)(xol + hb + oc) = (u32)l0 | ((u32)l1 << 16);
                }
            }
        }
    }
}

// ---------------------------------------------------------------------------
// Attention softmax (unchanged)
// ---------------------------------------------------------------------------
__global__ void attn_kernel(const float* __restrict__ out1,
                            const float* __restrict__ lin_w,
                            const float* __restrict__ lin_b,
                            float* __restrict__ attn)
{
    const int b = blockIdx.x, tid = threadIdx.x;
    const float* xb = out1 + (size_t)b * CIN * PP;
    float logit[16], lmax = -1e30f;
#pragma unroll
    for (int i = 0; i < 16; i++) {
        const int p = tid + i * 256;
        float acc = lin_b[p];
        const float4* wr = (const float4*)(lin_w + (size_t)p * CIN);
#pragma unroll
        for (int c4 = 0; c4 < CIN / 4; c4++) {
            float4 w4 = wr[c4];
            acc = fmaf(w4.x, xb[(c4*4+0)*PP + p], acc);
            acc = fmaf(w4.y, xb[(c4*4+1)*PP + p], acc);
            acc = fmaf(w4.z, xb[(c4*4+2)*PP + p], acc);
            acc = fmaf(w4.w, xb[(c4*4+3)*PP + p], acc);
        }
        logit[i] = acc; lmax = fmaxf(lmax, acc);
    }
    __shared__ float red[256];
    red[tid] = lmax; __syncthreads();
    for (int s = 128; s > 0; s >>= 1) { if (tid < s) red[tid] = fmaxf(red[tid], red[tid+s]); __syncthreads(); }
    const float m = red[0]; __syncthreads();
    float lsum = 0.f;
#pragma unroll
    for (int i = 0; i < 16; i++) { logit[i] = expf(logit[i] - m); lsum += logit[i]; }
    red[tid] = lsum; __syncthreads();
    for (int s = 128; s > 0; s >>= 1) { if (tid < s) red[tid] += red[tid+s]; __syncthreads(); }
    const float inv = 1.0f / red[0];
#pragma unroll
    for (int i = 0; i < 16; i++) attn[(size_t)b * PP + tid + i*256] = logit[i] * inv;
}

// ---------------------------------------------------------------------------
__global__ void bo3_kernel(const float* __restrict__ prev,
                           const float* __restrict__ attn,
                           float* __restrict__ out)
{
    const int idx = blockIdx.x * 256 + threadIdx.x;
    const int ox = idx & 31, oy = (idx >> 5) & 31, bc = idx >> 10;
    const int b = bc >> 7;
    const float* pv = prev + (size_t)bc * PP;
    const float* at = attn + (size_t)b * PP;
    const float BIN = 63.0f / 32.0f;
    float acc = 0.f;
#pragma unroll
    for (int sy = 0; sy < 2; sy++) {
        const float ys = ((float)oy + 0.25f + 0.5f * sy) * BIN;
        const int y0 = (int)ys, y1 = min(y0 + 1, HH - 1);
        const float ly = ys - (float)y0, hy = 1.f - ly;
#pragma unroll
        for (int sx = 0; sx < 2; sx++) {
            const float xs = ((float)ox + 0.25f + 0.5f * sx) * BIN;
            const int x0 = (int)xs, x1 = min(x0 + 1, WW - 1);
            const float lx = xs - (float)x0, hx = 1.f - lx;
            const float f00 = pv[y0*WW+x0]*at[y0*WW+x0], f01 = pv[y0*WW+x1]*at[y0*WW+x1];
            const float f10 = pv[y1*WW+x0]*at[y1*WW+x0], f11 = pv[y1*WW+x1]*at[y1*WW+x1];
            acc += hy * (hx*f00 + lx*f01) + ly * (hx*f10 + lx*f11);
        }
    }
    out[idx] = acc * 0.25f;
}

__global__ void combine_kernel(const float* __restrict__ l2,
                               const float* __restrict__ aux,
                               float* __restrict__ out)
{
    const int idx = blockIdx.x * 256 + threadIdx.x;
    const int ox = idx & 31, oy = (idx >> 5) & 31, bc = idx >> 10;
    const float* src = l2 + (size_t)bc * PP;
    const float BIN = 63.0f / 32.0f;
    float acc = 0.f;
#pragma unroll
    for (int sy = 0; sy < 2; sy++) {
        const float ys = ((float)oy + 0.25f + 0.5f * sy) * BIN;
        const int y0 = (int)ys, y1 = min(y0 + 1, HH - 1);
        const float ly = ys - (float)y0, hy = 1.f - ly;
#pragma unroll
        for (int sx = 0; sx < 2; sx++) {
            const float xs = ((float)ox + 0.25f + 0.5f * sx) * BIN;
            const int x0 = (int)xs, x1 = min(x0 + 1, WW - 1);
            const float lx = xs - (float)x0, hx = 1.f - lx;
            acc += hy * (hx*src[y0*WW+x0] + lx*src[y0*WW+x1])
                 + ly * (hx*src[y1*WW+x0] + lx*src[y1*WW+x1]);
        }
    }
    out[idx] = acc * 0.25f + aux[idx] + out[SLICE + idx] + out[2*SLICE + idx];
}

// ---------------------------------------------------------------------------
extern "C" void kernel_launch(void* const* d_in, const int* in_sizes, int n_in,
                              void* d_out, int out_size)
{
    const float* out1   = (const float*)d_in[0];
    const float* out2   = (const float*)d_in[1];
    const float* out3   = (const float*)d_in[2];
    const float* w1     = (const float*)d_in[3];
    const float* b1     = (const float*)d_in[4];
    const float* w2     = (const float*)d_in[5];
    const float* b2     = (const float*)d_in[6];
    const float* w3     = (const float*)d_in[7];
    const float* b3     = (const float*)d_in[8];
    const float* w_aux  = (const float*)d_in[9];
    const float* b_aux  = (const float*)d_in[10];
    const float* w_b2   = (const float*)d_in[11];
    const float* b_b2   = (const float*)d_in[12];
    const float* w_prev = (const float*)d_in[13];
    const float* b_prev = (const float*)d_in[14];
    const float* lin_w  = (const float*)d_in[15];
    const float* lin_b  = (const float*)d_in[16];
    float* out = (float*)d_out;

    float *l2, *prev, *aux, *attn;
    cudaGetSymbolAddress((void**)&l2,   g_l2);
    cudaGetSymbolAddress((void**)&prev, g_prev);
    cudaGetSymbolAddress((void**)&aux,  g_aux);
    cudaGetSymbolAddress((void**)&attn, g_attn);
    ush *x1h,*x1l,*x2h,*x2l,*x3h,*x3l,*x4h,*x4l,*xph,*xpl;
    ush *w1h,*w1l,*w2h,*w2l,*w3h,*w3l,*wph,*wpl,*wbh,*wbl,*wah,*wal;
    cudaGetSymbolAddress((void**)&x1h, g_x1h); cudaGetSymbolAddress((void**)&x1l, g_x1l);
    cudaGetSymbolAddress((void**)&x2h, g_x2h); cudaGetSymbolAddress((void**)&x2l, g_x2l);
    cudaGetSymbolAddress((void**)&x3h, g_x3h); cudaGetSymbolAddress((void**)&x3l, g_x3l);
    cudaGetSymbolAddress((void**)&x4h, g_x4h); cudaGetSymbolAddress((void**)&x4l, g_x4l);
    cudaGetSymbolAddress((void**)&xph, g_xph); cudaGetSymbolAddress((void**)&xpl, g_xpl);
    cudaGetSymbolAddress((void**)&w1h, g_w1h); cudaGetSymbolAddress((void**)&w1l, g_w1l);
    cudaGetSymbolAddress((void**)&w2h, g_w2h); cudaGetSymbolAddress((void**)&w2l, g_w2l);
    cudaGetSymbolAddress((void**)&w3h, g_w3h); cudaGetSymbolAddress((void**)&w3l, g_w3l);
    cudaGetSymbolAddress((void**)&wph, g_wph); cudaGetSymbolAddress((void**)&wpl, g_wpl);
    cudaGetSymbolAddress((void**)&wbh, g_wbh); cudaGetSymbolAddress((void**)&wbl, g_wbl);
    cudaGetSymbolAddress((void**)&wah, g_wah); cudaGetSymbolAddress((void**)&wal, g_wal);

    static cudaStream_t sB = nullptr, sC = nullptr;
    static cudaEvent_t eFork = nullptr, eL2 = nullptr, eB = nullptr, eC = nullptr;
    if (!sB) {
        cudaStreamCreateWithFlags(&sB, cudaStreamNonBlocking);
        cudaStreamCreateWithFlags(&sC, cudaStreamNonBlocking);
        cudaEventCreateWithFlags(&eFork, cudaEventDisableTiming);
        cudaEventCreateWithFlags(&eL2,   cudaEventDisableTiming);
        cudaEventCreateWithFlags(&eB,    cudaEventDisableTiming);
        cudaEventCreateWithFlags(&eC,    cudaEventDisableTiming);
    }

    const dim3 gsM1(32, 1, 32);      // stride-1 tensor convs (64x64 out)
    const dim3 gsM2(8, 1, 32);       // stride-2 tensor convs (32x32 out)
    const dim3 gsA(64, 32);          // asplit
    const int  nPix = (int)(SLICE / 256);

    cudaEventRecord(eFork, 0);
    cudaStreamWaitEvent(sB, eFork, 0);
    cudaStreamWaitEvent(sC, eFork, 0);

    // ---- stream B: attn + prev chain + bo3 ----
    attn_kernel<<<BB, 256, 0, sB>>>(out1, lin_w, lin_b, attn);
    wsplit<<<(128*128*9 + 255)/256, 256, 0, sB>>>(w_prev, 128, wph, wpl);
    asplit<128><<<gsA, 256, 0, sB>>>(out2, out3, 64, xph, xpl);
    mconv<2,1><<<gsM1, 256, 0, sB>>>(xph, xpl, xph, xpl, 2, wph, wpl, b_prev,
                                     prev, nullptr, nullptr);
    bo3_kernel<<<nPix, 256, 0, sB>>>(prev, attn, out + 2*SLICE);
    cudaEventRecord(eB, sB);

    // ---- stream C: w_b2 prep early; conv_b2 after l1,l2 HWC ready ----
    wsplit<<<(128*256*9 + 255)/256, 256, 0, sC>>>(w_b2, 256, wbh, wbl);

    // ---- main chain ----
    wsplit<<<(128*64*9  + 255)/256, 256>>>(w1, 64,  w1h, w1l);
    wsplit<<<(128*128*9 + 255)/256, 256>>>(w2, 128, w2h, w2l);
    wsplit<<<(128*128*9 + 255)/256, 256>>>(w3, 128, w3h, w3l);
    wsplit<<<(128*128*9 + 255)/256, 256>>>(w_aux, 128, wah, wal);
    asplit<64><<<gsA, 256>>>(out1, nullptr, 64, x1h, x1l);
    mconv<1,1><<<gsM1, 256>>>(x1h, x1l, x1h, x1l, 1, w1h, w1l, b1,
                              nullptr, x2h, x2l);                       // l1 (HWC only)
    mconv<2,1><<<gsM1, 256>>>(x2h, x2l, x2h, x2l, 2, w2h, w2l, b2,
                              l2, x3h, x3l);                            // l2

    cudaEventRecord(eL2, 0);
    cudaStreamWaitEvent(sC, eL2, 0);
    mconv<4,2><<<gsM2, 256, 0, sC>>>(x2h, x2l, x3h, x3l, 2, wbh, wbl, b_b2,
                                     out + SLICE, nullptr, nullptr);    // block_out2
    cudaEventRecord(eC, sC);

    mconv<2,1><<<gsM1, 256>>>(x3h, x3l, x3h, x3l, 2, w3h, w3l, b3,
                              nullptr, x4h, x4l);                       // l3 (HWC only)
    mconv<2,2><<<gsM2, 256>>>(x4h, x4l, x4h, x4l, 2, wah, wal, b_aux,
                              aux, nullptr, nullptr);                   // aux

    cudaStreamWaitEvent(0, eB, 0);
    cudaStreamWaitEvent(0, eC, 0);
    combine_kernel<<<nPix, 256>>>(l2, aux, out);
}

// round 14
// speedup vs baseline: 3.0885x; 1.1506x over previous
#include <cuda_runtime.h>

#define BB   32
#define CIN  64
#define OCH  128
#define HH   64
#define WW   64
#define PP   (HH*WW)
#define OH   32
#define OW   32
#define SLICE ((size_t)BB*OCH*OH*OW)

typedef unsigned long long u64;
typedef unsigned int u32;
typedef unsigned short ush;

// ---------------- scratch (device globals) ----------------
__device__ float g_l2  [BB*OCH*HH*WW];
__device__ float g_prev[BB*OCH*HH*WW];
__device__ float g_aux [BB*OCH*OH*OW];
__device__ float g_attn[BB*PP];
// HWC bf16 hi/lo activation buffers
__device__ ush g_x1h[BB*PP*64],  g_x1l[BB*PP*64];     // out1
__device__ ush g_x2h[BB*PP*128], g_x2l[BB*PP*128];    // l1
__device__ ush g_x3h[BB*PP*128], g_x3l[BB*PP*128];    // l2
__device__ ush g_x4h[BB*PP*128], g_x4l[BB*PP*128];    // l3
__device__ ush g_xph[BB*PP*128], g_xpl[BB*PP*128];    // concat(out2,out3)
// weight B-tiles: [tap][cib][128 oc][64 ci]
__device__ ush g_w1h[9*1*128*64], g_w1l[9*1*128*64];
__device__ ush g_w2h[9*2*128*64], g_w2l[9*2*128*64];
__device__ ush g_w3h[9*2*128*64], g_w3l[9*2*128*64];
__device__ ush g_wph[9*2*128*64], g_wpl[9*2*128*64];
__device__ ush g_wbh[9*4*128*64], g_wbl[9*4*128*64];  // w_b2 (CI=256)
__device__ ush g_wah[9*2*128*64], g_wal[9*2*128*64];  // w_aux

__device__ __forceinline__ float lrelu(float x) { return x >= 0.f ? x : 0.1f * x; }

// ---- bf16 split ----
__device__ __forceinline__ u32 bf16rn(float x) {
    u32 u = __float_as_uint(x);
    return (u + 0x7FFFu + ((u >> 16) & 1u)) >> 16;
}
__device__ __forceinline__ void bsplit(float x, ush& h, ush& l) {
    u32 uh = bf16rn(x); h = (ush)uh;
    float fh = __uint_as_float(uh << 16);
    l = (ush)bf16rn(x - fh);
}

__device__ __forceinline__ u32 smem_u32(const void* p) {
    u32 a; asm("{ .reg .u64 t; cvta.to.shared.u64 t, %1; cvt.u32.u64 %0, t; }" : "=r"(a) : "l"(p));
    return a;
}
// ldmatrix x4 (sm_75+ baseline PTX)
__device__ __forceinline__ void ldm4(u32* r, u32 a) {
    asm volatile("ldmatrix.sync.aligned.m8n8.x4.shared.b16 {%0,%1,%2,%3}, [%4];"
        : "=r"(r[0]), "=r"(r[1]), "=r"(r[2]), "=r"(r[3]) : "r"(a));
}
// mma.sync bf16 (sm_80+ baseline PTX) -> HMMA on Blackwell
__device__ __forceinline__ void mma16816(float* c, const u32* a, u32 b0, u32 b1) {
    asm volatile("mma.sync.aligned.m16n8k16.row.col.f32.bf16.bf16.f32 "
        "{%0,%1,%2,%3}, {%4,%5,%6,%7}, {%8,%9}, {%0,%1,%2,%3};"
        : "+f"(c[0]), "+f"(c[1]), "+f"(c[2]), "+f"(c[3])
        : "r"(a[0]), "r"(a[1]), "r"(a[2]), "r"(a[3]), "r"(b0), "r"(b1));
}

// ---------------------------------------------------------------------------
// Prep: NCHW fp32 (optionally concat of two) -> HWC bf16 hi/lo
// ---------------------------------------------------------------------------
template<int CI>
__global__ __launch_bounds__(256)
void asplit(const float* __restrict__ s0, const float* __restrict__ s1, int csplit,
            ush* __restrict__ oh, ush* __restrict__ ol)
{
    __shared__ float t[CI][65];
    const int b = blockIdx.y, p0 = blockIdx.x * 64;
    for (int f = threadIdx.x; f < CI * 16; f += 256) {
        int ci = f >> 4, c4 = (f & 15) * 4;
        const float* src = (ci < csplit)
            ? s0 + ((size_t)b * csplit + ci) * PP
            : s1 + ((size_t)b * (CI - csplit) + ci - csplit) * PP;
        float4 v = *(const float4*)(src + p0 + c4);
        t[ci][c4] = v.x; t[ci][c4+1] = v.y; t[ci][c4+2] = v.z; t[ci][c4+3] = v.w;
    }
    __syncthreads();
    for (int cid = threadIdx.x; cid < 64 * (CI / 8); cid += 256) {
        int px = cid / (CI / 8), k8 = cid % (CI / 8);
        u32 hu[4], lu[4];
#pragma unroll
        for (int j = 0; j < 4; j++) {
            ush h0, l0, h1, l1;
            bsplit(t[k8*8 + 2*j][px],     h0, l0);
            bsplit(t[k8*8 + 2*j + 1][px], h1, l1);
            hu[j] = (u32)h0 | ((u32)h1 << 16);
            lu[j] = (u32)l0 | ((u32)l1 << 16);
        }
        size_t off = ((size_t)b * PP + p0 + px) * CI + k8 * 8;
        *(uint4*)(oh + off) = *(uint4*)hu;
        *(uint4*)(ol + off) = *(uint4*)lu;
    }
}

// Prep: weights [128][CI][3][3] fp32 -> [tap][cib][128][64] bf16 hi/lo
__global__ void wsplit(const float* __restrict__ w, int CI,
                       ush* __restrict__ oh, ush* __restrict__ ol)
{
    int i = blockIdx.x * 256 + threadIdx.x;
    if (i >= 128 * CI * 9) return;
    int oc = i / (CI * 9), r = i % (CI * 9), ci = r / 9, tap = r % 9;
    ush h, l; bsplit(w[i], h, l);
    size_t o = (((size_t)(tap * (CI >> 6) + (ci >> 6)) * 128 + oc) * 64 + (ci & 63));
    oh[o] = h; ol[o] = l;
}

// ---------------------------------------------------------------------------
// Tensor-core 3x3 conv (stride 1 or 2) via mma.sync bf16 hi/lo.
// Halo-slab A staging: one fill per (cib,kc) stage serves all 9 taps.
// W double-buffered, 1 barrier per tap.  CTA: 256 thr (8 warps 2x4).
// D = 128 out-px x 128 oc in registers.
// ---------------------------------------------------------------------------
template<int CIB, int STRIDE>
__global__ __launch_bounds__(256, 2)
void mconv(const ush* __restrict__ ah, const ush* __restrict__ al,
           const ush* __restrict__ ah2, const ush* __restrict__ al2, int cib1,
           const ush* __restrict__ wh, const ush* __restrict__ wl,
           const float* __restrict__ bias, float* __restrict__ outw,
           ush* __restrict__ xoh, ush* __restrict__ xol)
{
    constexpr int OWO   = WW / STRIDE;            // out width
    constexpr int ROWS  = 128 / OWO;              // out rows per tile
    constexpr int PPO   = (HH / STRIDE) * OWO;    // out pixels per channel
    constexpr int SROWS = STRIDE * (ROWS - 1) + 3;
    constexpr int SLOTS = SROWS * 68;
    constexpr int SLABH = SLOTS * 32;             // bytes of hi slab
    constexpr int W_OFF = 2 * SLABH;              // W region
    constexpr int NST   = 4 * CIB;
    constexpr int NG    = NST * 9;

    extern __shared__ __align__(16) char sm[];
    float* sbias = (float*)(sm + W_OFF + 16384);

    const int tid  = threadIdx.x;
    const int lane = tid & 31, wid = tid >> 5;
    const int wm = wid >> 2, wn = wid & 3;        // warp tile coords (2 x 4)
    const int b = blockIdx.z, y0 = blockIdx.x * ROWS;

    if (tid < 128) sbias[tid] = bias[tid];

    const int CI1 = cib1 * 64, CI2 = CIB * 64 - CI1;
    const u32 sSlab = smem_u32(sm);
    const u32 sWb   = smem_u32(sm + W_OFF);

    auto xv = [](int c) -> u32 {
        return (STRIDE == 1) ? (u32)((c & 4) << 2) : (u32)((c & 12) << 2);
    };

    float acc[4][4][4];
#pragma unroll
    for (int mt = 0; mt < 4; mt++)
#pragma unroll
        for (int nt = 0; nt < 4; nt++)
#pragma unroll
            for (int r = 0; r < 4; r++) acc[mt][nt][r] = 0.f;

    const uint4 z4 = make_uint4(0, 0, 0, 0);
    uint4 wvh, wvl;

    // ---- A slab fill for stage st = (cib, kc) ----
    auto fillA = [&](int st) {
        const int cib = st >> 2, kc = st & 3;
        const int ci = cib * 64 + kc * 16;
        for (int i = tid; i < SLOTS; i += 256) {
            const int sr = i / 68, sc = i - sr * 68;
            if (sc >= 66) continue;
            const int y = STRIDE * y0 + sr - 1, x = sc - 1;
            const bool ok = ((unsigned)y < HH) & ((unsigned)x < WW);
            const ush *ph, *pl;
            if (ci < CI1) {
                size_t off = ((size_t)b * PP + y * WW + x) * (size_t)CI1 + ci;
                ph = ah + off; pl = al + off;
            } else {
                size_t off = ((size_t)b * PP + y * WW + x) * (size_t)CI2 + (ci - CI1);
                ph = ah2 + off; pl = al2 + off;
            }
            uint4 h0 = ok ? *(const uint4*)ph        : z4;
            uint4 h1 = ok ? *(const uint4*)(ph + 8)  : z4;
            uint4 l0 = ok ? *(const uint4*)pl        : z4;
            uint4 l1 = ok ? *(const uint4*)(pl + 8)  : z4;
            const u32 base = (u32)i * 32, xr = xv(sc);
            *(uint4*)(sm + ((base)      ^ xr))          = h0;
            *(uint4*)(sm + ((base + 16) ^ xr))          = h1;
            *(uint4*)(sm + SLABH + ((base)      ^ xr))  = l0;
            *(uint4*)(sm + SLABH + ((base + 16) ^ xr))  = l1;
        }
    };
    // ---- W tile LDG for global step g = st*9 + tap ----
    auto ldgW = [&](int g) {
        const int st = g / 9, tap = g - st * 9;
        const int cib = st >> 2, kc = st & 3;
        size_t off = ((size_t)(tap * CIB + cib) * 128 + (tid >> 1)) * 64
                   + kc * 16 + (tid & 1) * 8;
        wvh = *(const uint4*)(wh + off);
        wvl = *(const uint4*)(wl + off);
    };
    auto stsW = [&](int buf) {
        const int row = tid >> 1, cc = tid & 1;
        const int ch = cc ^ ((row >> 2) & 1);
        char* base = sm + W_OFF + buf * 8192 + row * 32 + ch * 16;
        *(uint4*)base          = wvh;
        *(uint4*)(base + 4096) = wvl;
    };

    // prologue
    fillA(0);
    ldgW(0); stsW(0);
    __syncthreads();

    int g = 0;
    for (int st = 0; st < NST; st++) {
        for (int tap = 0; tap < 9; tap++, g++) {
            const int buf = g & 1;
            if (g + 1 < NG) ldgW(g + 1);
            const int ky = tap / 3, kx = tap - ky * 3;

            // ---- W fragments via ldmatrix ----
            u32 bh[4][2], bl[4][2];
            const u32 wbase = sWb + buf * 8192;
#pragma unroll
            for (int ntp = 0; ntp < 2; ntp++) {
                const int sel = lane >> 3;
                const int row = wn * 32 + ntp * 16 + ((sel & 2) << 2) + (lane & 7);
                const int ch = (sel & 1) ^ ((row >> 2) & 1);
                const u32 ad = wbase + row * 32 + ch * 16;
                u32 r[4];
                ldm4(r, ad);
                bh[ntp*2][0] = r[0]; bh[ntp*2][1] = r[1];
                bh[ntp*2+1][0] = r[2]; bh[ntp*2+1][1] = r[3];
                ldm4(r, ad + 4096);
                bl[ntp*2][0] = r[0]; bl[ntp*2][1] = r[1];
                bl[ntp*2+1][0] = r[2]; bl[ntp*2+1][1] = r[3];
            }

            // ---- A fragments from slab + mma ----
#pragma unroll
            for (int mt = 0; mt < 4; mt++) {
                const int p  = wm * 64 + mt * 16 + (lane & 15);
                const int oy = p / OWO, ox = p - oy * OWO;
                const int col = STRIDE * ox + kx;
                const int srow = STRIDE * oy + ky;
                const u32 byte = (u32)(srow * 68 + col) * 32 + (u32)(lane >> 4) * 16;
                const u32 ao = sSlab + (byte ^ xv(col));
                u32 ahr[4], alr[4];
                ldm4(ahr, ao);
                ldm4(alr, ao + SLABH);
#pragma unroll
                for (int nt = 0; nt < 4; nt++) {
                    mma16816(acc[mt][nt], ahr, bh[nt][0], bh[nt][1]);   // hi*hi
                    mma16816(acc[mt][nt], ahr, bl[nt][0], bl[nt][1]);   // hi*lo
                    mma16816(acc[mt][nt], alr, bh[nt][0], bh[nt][1]);   // lo*hi
                }
            }

            if (g + 1 < NG) stsW(buf ^ 1);
            __syncthreads();
        }
        if (st + 1 < NST) { fillA(st + 1); __syncthreads(); }
    }

    // epilogue: bias + lrelu; optional NCHW fp32 write; optional HWC hi/lo write
    const int r0 = lane >> 2, cp = (lane & 3) * 2;
#pragma unroll
    for (int mt = 0; mt < 4; mt++) {
#pragma unroll
        for (int half = 0; half < 2; half++) {
            const int px = wm * 64 + mt * 16 + r0 + half * 8;
            const int y = y0 + px / OWO, x = px % OWO;
            const size_t nb = (((size_t)b * OCH) * (size_t)(HH / STRIDE) + y) * OWO + x;
            const size_t hb = ((size_t)b * PP + y * WW + x) * 128;
#pragma unroll
            for (int nt = 0; nt < 4; nt++) {
                const int oc = wn * 32 + nt * 8 + cp;
                const float f0 = lrelu(acc[mt][nt][half * 2 + 0] + sbias[oc]);
                const float f1 = lrelu(acc[mt][nt][half * 2 + 1] + sbias[oc + 1]);
                if (outw) {
                    outw[nb + (size_t)oc * PPO]       = f0;
                    outw[nb + (size_t)(oc + 1) * PPO] = f1;
                }
                if (xoh) {
                    ush h0, l0, h1, l1;
                    bsplit(f0, h0, l0); bsplit(f1, h1, l1);
                    *(u32*)(xoh + hb + oc) = (u32)h0 | ((u32)h1 << 16);
                    *(u32*)(xol + hb + oc) = (u32)l0 | ((u32)l1 << 16);
                }
            }
        }
    }
}

// smem sizes per instantiation
#define MC_SMEM(STRIDE) ((2 * ((STRIDE*1 + 3 - STRIDE + STRIDE*(128/(WW/STRIDE)-1) + 3) * 0 + \
                          (STRIDE*((128/(WW/STRIDE))-1)+3) * 68 * 32)) + 16384 + 512)

// ---------------------------------------------------------------------------
// Attention softmax (unchanged)
// ---------------------------------------------------------------------------
__global__ void attn_kernel(const float* __restrict__ out1,
                            const float* __restrict__ lin_w,
                            const float* __restrict__ lin_b,
                            float* __restrict__ attn)
{
    const int b = blockIdx.x, tid = threadIdx.x;
    const float* xb = out1 + (size_t)b * CIN * PP;
    float logit[16], lmax = -1e30f;
#pragma unroll
    for (int i = 0; i < 16; i++) {
        const int p = tid + i * 256;
        float acc = lin_b[p];
        const float4* wr = (const float4*)(lin_w + (size_t)p * CIN);
#pragma unroll
        for (int c4 = 0; c4 < CIN / 4; c4++) {
            float4 w4 = wr[c4];
            acc = fmaf(w4.x, xb[(c4*4+0)*PP + p], acc);
            acc = fmaf(w4.y, xb[(c4*4+1)*PP + p], acc);
            acc = fmaf(w4.z, xb[(c4*4+2)*PP + p], acc);
            acc = fmaf(w4.w, xb[(c4*4+3)*PP + p], acc);
        }
        logit[i] = acc; lmax = fmaxf(lmax, acc);
    }
    __shared__ float red[256];
    red[tid] = lmax; __syncthreads();
    for (int s = 128; s > 0; s >>= 1) { if (tid < s) red[tid] = fmaxf(red[tid], red[tid+s]); __syncthreads(); }
    const float m = red[0]; __syncthreads();
    float lsum = 0.f;
#pragma unroll
    for (int i = 0; i < 16; i++) { logit[i] = expf(logit[i] - m); lsum += logit[i]; }
    red[tid] = lsum; __syncthreads();
    for (int s = 128; s > 0; s >>= 1) { if (tid < s) red[tid] += red[tid+s]; __syncthreads(); }
    const float inv = 1.0f / red[0];
#pragma unroll
    for (int i = 0; i < 16; i++) attn[(size_t)b * PP + tid + i*256] = logit[i] * inv;
}

// ---------------------------------------------------------------------------
__global__ void bo3_kernel(const float* __restrict__ prev,
                           const float* __restrict__ attn,
                           float* __restrict__ out)
{
    const int idx = blockIdx.x * 256 + threadIdx.x;
    const int ox = idx & 31, oy = (idx >> 5) & 31, bc = idx >> 10;
    const int b = bc >> 7;
    const float* pv = prev + (size_t)bc * PP;
    const float* at = attn + (size_t)b * PP;
    const float BIN = 63.0f / 32.0f;
    float acc = 0.f;
#pragma unroll
    for (int sy = 0; sy < 2; sy++) {
        const float ys = ((float)oy + 0.25f + 0.5f * sy) * BIN;
        const int y0 = (int)ys, y1 = min(y0 + 1, HH - 1);
        const float ly = ys - (float)y0, hy = 1.f - ly;
#pragma unroll
        for (int sx = 0; sx < 2; sx++) {
            const float xs = ((float)ox + 0.25f + 0.5f * sx) * BIN;
            const int x0 = (int)xs, x1 = min(x0 + 1, WW - 1);
            const float lx = xs - (float)x0, hx = 1.f - lx;
            const float f00 = pv[y0*WW+x0]*at[y0*WW+x0], f01 = pv[y0*WW+x1]*at[y0*WW+x1];
            const float f10 = pv[y1*WW+x0]*at[y1*WW+x0], f11 = pv[y1*WW+x1]*at[y1*WW+x1];
            acc += hy * (hx*f00 + lx*f01) + ly * (hx*f10 + lx*f11);
        }
    }
    out[idx] = acc * 0.25f;
}

__global__ void combine_kernel(const float* __restrict__ l2,
                               const float* __restrict__ aux,
                               float* __restrict__ out)
{
    const int idx = blockIdx.x * 256 + threadIdx.x;
    const int ox = idx & 31, oy = (idx >> 5) & 31, bc = idx >> 10;
    const float* src = l2 + (size_t)bc * PP;
    const float BIN = 63.0f / 32.0f;
    float acc = 0.f;
#pragma unroll
    for (int sy = 0; sy < 2; sy++) {
        const float ys = ((float)oy + 0.25f + 0.5f * sy) * BIN;
        const int y0 = (int)ys, y1 = min(y0 + 1, HH - 1);
        const float ly = ys - (float)y0, hy = 1.f - ly;
#pragma unroll
        for (int sx = 0; sx < 2; sx++) {
            const float xs = ((float)ox + 0.25f + 0.5f * sx) * BIN;
            const int x0 = (int)xs, x1 = min(x0 + 1, WW - 1);
            const float lx = xs - (float)x0, hx = 1.f - lx;
            acc += hy * (hx*src[y0*WW+x0] + lx*src[y0*WW+x1])
                 + ly * (hx*src[y1*WW+x0] + lx*src[y1*WW+x1]);
        }
    }
    out[idx] = acc * 0.25f + aux[idx] + out[SLICE + idx] + out[2*SLICE + idx];
}

// ---------------------------------------------------------------------------
extern "C" void kernel_launch(void* const* d_in, const int* in_sizes, int n_in,
                              void* d_out, int out_size)
{
    const float* out1   = (const float*)d_in[0];
    const float* out2   = (const float*)d_in[1];
    const float* out3   = (const float*)d_in[2];
    const float* w1     = (const float*)d_in[3];
    const float* b1     = (const float*)d_in[4];
    const float* w2     = (const float*)d_in[5];
    const float* b2     = (const float*)d_in[6];
    const float* w3     = (const float*)d_in[7];
    const float* b3     = (const float*)d_in[8];
    const float* w_aux  = (const float*)d_in[9];
    const float* b_aux  = (const float*)d_in[10];
    const float* w_b2   = (const float*)d_in[11];
    const float* b_b2   = (const float*)d_in[12];
    const float* w_prev = (const float*)d_in[13];
    const float* b_prev = (const float*)d_in[14];
    const float* lin_w  = (const float*)d_in[15];
    const float* lin_b  = (const float*)d_in[16];
    float* out = (float*)d_out;

    float *l2, *prev, *aux, *attn;
    cudaGetSymbolAddress((void**)&l2,   g_l2);
    cudaGetSymbolAddress((void**)&prev, g_prev);
    cudaGetSymbolAddress((void**)&aux,  g_aux);
    cudaGetSymbolAddress((void**)&attn, g_attn);
    ush *x1h,*x1l,*x2h,*x2l,*x3h,*x3l,*x4h,*x4l,*xph,*xpl;
    ush *w1h,*w1l,*w2h,*w2l,*w3h,*w3l,*wph,*wpl,*wbh,*wbl,*wah,*wal;
    cudaGetSymbolAddress((void**)&x1h, g_x1h); cudaGetSymbolAddress((void**)&x1l, g_x1l);
    cudaGetSymbolAddress((void**)&x2h, g_x2h); cudaGetSymbolAddress((void**)&x2l, g_x2l);
    cudaGetSymbolAddress((void**)&x3h, g_x3h); cudaGetSymbolAddress((void**)&x3l, g_x3l);
    cudaGetSymbolAddress((void**)&x4h, g_x4h); cudaGetSymbolAddress((void**)&x4l, g_x4l);
    cudaGetSymbolAddress((void**)&xph, g_xph); cudaGetSymbolAddress((void**)&xpl, g_xpl);
    cudaGetSymbolAddress((void**)&w1h, g_w1h); cudaGetSymbolAddress((void**)&w1l, g_w1l);
    cudaGetSymbolAddress((void**)&w2h, g_w2h); cudaGetSymbolAddress((void**)&w2l, g_w2l);
    cudaGetSymbolAddress((void**)&w3h, g_w3h); cudaGetSymbolAddress((void**)&w3l, g_w3l);
    cudaGetSymbolAddress((void**)&wph, g_wph); cudaGetSymbolAddress((void**)&wpl, g_wpl);
    cudaGetSymbolAddress((void**)&wbh, g_wbh); cudaGetSymbolAddress((void**)&wbl, g_wbl);
    cudaGetSymbolAddress((void**)&wah, g_wah); cudaGetSymbolAddress((void**)&wal, g_wal);

    static cudaStream_t sB = nullptr, sC = nullptr;
    static cudaEvent_t eFork = nullptr, eL2 = nullptr, eB = nullptr, eC = nullptr, eW = nullptr;
    if (!sB) {
        cudaStreamCreateWithFlags(&sB, cudaStreamNonBlocking);
        cudaStreamCreateWithFlags(&sC, cudaStreamNonBlocking);
        cudaEventCreateWithFlags(&eFork, cudaEventDisableTiming);
        cudaEventCreateWithFlags(&eL2,   cudaEventDisableTiming);
        cudaEventCreateWithFlags(&eB,    cudaEventDisableTiming);
        cudaEventCreateWithFlags(&eC,    cudaEventDisableTiming);
        cudaEventCreateWithFlags(&eW,    cudaEventDisableTiming);
    }

    // dynamic smem sizes: slab(hi+lo) + W dbuf + bias
    const int smem_s1 = 2 * (4 * 68 * 32) + 16384 + 512;   // 34304
    const int smem_s2 = 2 * (9 * 68 * 32) + 16384 + 512;   // 56064
    cudaFuncSetAttribute(mconv<1,1>, cudaFuncAttributeMaxDynamicSharedMemorySize, smem_s1);
    cudaFuncSetAttribute(mconv<2,1>, cudaFuncAttributeMaxDynamicSharedMemorySize, smem_s1);
    cudaFuncSetAttribute(mconv<2,2>, cudaFuncAttributeMaxDynamicSharedMemorySize, smem_s2);
    cudaFuncSetAttribute(mconv<4,2>, cudaFuncAttributeMaxDynamicSharedMemorySize, smem_s2);

    const dim3 gsM1(32, 1, 32);      // stride-1 tensor convs (64x64 out, 2 rows/CTA)
    const dim3 gsM2(8, 1, 32);       // stride-2 tensor convs (32x32 out, 4 rows/CTA)
    const dim3 gsA(64, 32);          // asplit
    const int  nPix = (int)(SLICE / 256);

    cudaEventRecord(eFork, 0);
    cudaStreamWaitEvent(sB, eFork, 0);
    cudaStreamWaitEvent(sC, eFork, 0);

    // ---- stream B: attn + prev chain + bo3 ----
    attn_kernel<<<BB, 256, 0, sB>>>(out1, lin_w, lin_b, attn);
    wsplit<<<(128*128*9 + 255)/256, 256, 0, sB>>>(w_prev, 128, wph, wpl);
    asplit<128><<<gsA, 256, 0, sB>>>(out2, out3, 64, xph, xpl);
    mconv<2,1><<<gsM1, 256, smem_s1, sB>>>(xph, xpl, xph, xpl, 2, wph, wpl, b_prev,
                                           prev, nullptr, nullptr);
    bo3_kernel<<<nPix, 256, 0, sB>>>(prev, attn, out + 2*SLICE);
    cudaEventRecord(eB, sB);

    // ---- stream C: weight preps off critical path ----
    wsplit<<<(128*128*9 + 255)/256, 256, 0, sC>>>(w2, 128, w2h, w2l);
    wsplit<<<(128*128*9 + 255)/256, 256, 0, sC>>>(w3, 128, w3h, w3l);
    wsplit<<<(128*128*9 + 255)/256, 256, 0, sC>>>(w_aux, 128, wah, wal);
    wsplit<<<(128*256*9 + 255)/256, 256, 0, sC>>>(w_b2, 256, wbh, wbl);
    cudaEventRecord(eW, sC);

    // ---- main chain ----
    wsplit<<<(128*64*9 + 255)/256, 256>>>(w1, 64, w1h, w1l);
    asplit<64><<<gsA, 256>>>(out1, nullptr, 64, x1h, x1l);
    mconv<1,1><<<gsM1, 256, smem_s1>>>(x1h, x1l, x1h, x1l, 1, w1h, w1l, b1,
                                       nullptr, x2h, x2l);              // l1 (HWC only)
    cudaStreamWaitEvent(0, eW, 0);
    mconv<2,1><<<gsM1, 256, smem_s1>>>(x2h, x2l, x2h, x2l, 2, w2h, w2l, b2,
                                       l2, x3h, x3l);                   // l2

    cudaEventRecord(eL2, 0);
    cudaStreamWaitEvent(sC, eL2, 0);
    mconv<4,2><<<gsM2, 256, smem_s2, sC>>>(x2h, x2l, x3h, x3l, 2, wbh, wbl, b_b2,
                                           out + SLICE, nullptr, nullptr);  // block_out2
    cudaEventRecord(eC, sC);

    mconv<2,1><<<gsM1, 256, smem_s1>>>(x3h, x3l, x3h, x3l, 2, w3h, w3l, b3,
                                       nullptr, x4h, x4l);              // l3 (HWC only)
    mconv<2,2><<<gsM2, 256, smem_s2>>>(x4h, x4l, x4h, x4l, 2, wah, wal, b_aux,
                                       aux, nullptr, nullptr);          // aux

    cudaStreamWaitEvent(0, eB, 0);
    cudaStreamWaitEvent(0, eC, 0);
    combine_kernel<<<nPix, 256>>>(l2, aux, out);
}

// round 15
// speedup vs baseline: 3.1737x; 1.0276x over previous
#include <cuda_runtime.h>

#define BB   32
#define CIN  64
#define OCH  128
#define HH   64
#define WW   64
#define PP   (HH*WW)
#define OH   32
#define OW   32
#define SLICE ((size_t)BB*OCH*OH*OW)

typedef unsigned long long u64;
typedef unsigned int u32;
typedef unsigned short ush;

// ---------------- scratch (device globals) ----------------
__device__ float g_l2  [BB*OCH*HH*WW];
__device__ float g_prev[BB*OCH*HH*WW];
__device__ float g_aux [BB*OCH*OH*OW];
__device__ float g_attn[BB*PP];
// HWC bf16 hi/lo activation buffers
__device__ ush g_x1h[BB*PP*64],  g_x1l[BB*PP*64];     // out1
__device__ ush g_x2h[BB*PP*128], g_x2l[BB*PP*128];    // l1
__device__ ush g_x3h[BB*PP*128], g_x3l[BB*PP*128];    // l2
__device__ ush g_x4h[BB*PP*128], g_x4l[BB*PP*128];    // l3
__device__ ush g_xph[BB*PP*128], g_xpl[BB*PP*128];    // concat(out2,out3)
// weight B-tiles: [tap][cib][128 oc][64 ci]
__device__ ush g_w1h[9*1*128*64], g_w1l[9*1*128*64];
__device__ ush g_w2h[9*2*128*64], g_w2l[9*2*128*64];
__device__ ush g_w3h[9*2*128*64], g_w3l[9*2*128*64];
__device__ ush g_wph[9*2*128*64], g_wpl[9*2*128*64];
__device__ ush g_wbh[9*4*128*64], g_wbl[9*4*128*64];  // w_b2 (CI=256)
__device__ ush g_wah[9*2*128*64], g_wal[9*2*128*64];  // w_aux

__device__ __forceinline__ float lrelu(float x) { return x >= 0.f ? x : 0.1f * x; }

// ---- bf16 split ----
__device__ __forceinline__ u32 bf16rn(float x) {
    u32 u = __float_as_uint(x);
    return (u + 0x7FFFu + ((u >> 16) & 1u)) >> 16;
}
__device__ __forceinline__ void bsplit(float x, ush& h, ush& l) {
    u32 uh = bf16rn(x); h = (ush)uh;
    float fh = __uint_as_float(uh << 16);
    l = (ush)bf16rn(x - fh);
}

__device__ __forceinline__ u32 smem_u32(const void* p) {
    u32 a; asm("{ .reg .u64 t; cvta.to.shared.u64 t, %1; cvt.u32.u64 %0, t; }" : "=r"(a) : "l"(p));
    return a;
}
// ldmatrix x4 (sm_75+ baseline PTX)
__device__ __forceinline__ void ldm4(u32* r, u32 a) {
    asm volatile("ldmatrix.sync.aligned.m8n8.x4.shared.b16 {%0,%1,%2,%3}, [%4];"
        : "=r"(r[0]), "=r"(r[1]), "=r"(r[2]), "=r"(r[3]) : "r"(a));
}
// mma.sync bf16 (sm_80+ baseline PTX) -> HMMA on Blackwell
__device__ __forceinline__ void mma16816(float* c, const u32* a, u32 b0, u32 b1) {
    asm volatile("mma.sync.aligned.m16n8k16.row.col.f32.bf16.bf16.f32 "
        "{%0,%1,%2,%3}, {%4,%5,%6,%7}, {%8,%9}, {%0,%1,%2,%3};"
        : "+f"(c[0]), "+f"(c[1]), "+f"(c[2]), "+f"(c[3])
        : "r"(a[0]), "r"(a[1]), "r"(a[2]), "r"(a[3]), "r"(b0), "r"(b1));
}
// cp.async 16B (sm_80+ baseline PTX); src_size<16 zero-fills remainder
__device__ __forceinline__ void cpa16(u32 dst, const void* src, u32 sz) {
    asm volatile("cp.async.cg.shared.global [%0], [%1], 16, %2;"
        :: "r"(dst), "l"(src), "r"(sz) : "memory");
}
__device__ __forceinline__ void cpa_commit() {
    asm volatile("cp.async.commit_group;" ::: "memory");
}
__device__ __forceinline__ void cpa_wait0() {
    asm volatile("cp.async.wait_group 0;" ::: "memory");
}

// ---------------------------------------------------------------------------
// Prep: NCHW fp32 (optionally concat of two) -> HWC bf16 hi/lo
// ---------------------------------------------------------------------------
template<int CI>
__global__ __launch_bounds__(256)
void asplit(const float* __restrict__ s0, const float* __restrict__ s1, int csplit,
            ush* __restrict__ oh, ush* __restrict__ ol)
{
    __shared__ float t[CI][65];
    const int b = blockIdx.y, p0 = blockIdx.x * 64;
    for (int f = threadIdx.x; f < CI * 16; f += 256) {
        int ci = f >> 4, c4 = (f & 15) * 4;
        const float* src = (ci < csplit)
            ? s0 + ((size_t)b * csplit + ci) * PP
            : s1 + ((size_t)b * (CI - csplit) + ci - csplit) * PP;
        float4 v = *(const float4*)(src + p0 + c4);
        t[ci][c4] = v.x; t[ci][c4+1] = v.y; t[ci][c4+2] = v.z; t[ci][c4+3] = v.w;
    }
    __syncthreads();
    for (int cid = threadIdx.x; cid < 64 * (CI / 8); cid += 256) {
        int px = cid / (CI / 8), k8 = cid % (CI / 8);
        u32 hu[4], lu[4];
#pragma unroll
        for (int j = 0; j < 4; j++) {
            ush h0, l0, h1, l1;
            bsplit(t[k8*8 + 2*j][px],     h0, l0);
            bsplit(t[k8*8 + 2*j + 1][px], h1, l1);
            hu[j] = (u32)h0 | ((u32)h1 << 16);
            lu[j] = (u32)l0 | ((u32)l1 << 16);
        }
        size_t off = ((size_t)b * PP + p0 + px) * CI + k8 * 8;
        *(uint4*)(oh + off) = *(uint4*)hu;
        *(uint4*)(ol + off) = *(uint4*)lu;
    }
}

// Prep: weights [128][CI][3][3] fp32 -> [tap][cib][128][64] bf16 hi/lo
__global__ void wsplit(const float* __restrict__ w, int CI,
                       ush* __restrict__ oh, ush* __restrict__ ol)
{
    int i = blockIdx.x * 256 + threadIdx.x;
    if (i >= 128 * CI * 9) return;
    int oc = i / (CI * 9), r = i % (CI * 9), ci = r / 9, tap = r % 9;
    ush h, l; bsplit(w[i], h, l);
    size_t o = (((size_t)(tap * (CI >> 6) + (ci >> 6)) * 128 + oc) * 64 + (ci & 63));
    oh[o] = h; ol[o] = l;
}

// ---------------------------------------------------------------------------
// Stride-1 tensor conv, restructured:
//  - A slab: full 64ci per cib, filled ONCE per cib via cp.async (zero-fill halo)
//  - W: double-buffered 16KB (tap, kc-half) tiles via cp.async, latency hidden
//  - inner loop barrier-free; ~38 barriers total
// CTA: 256 thr (8 warps 2x4); D = 128 px x 128 oc in registers.
// ---------------------------------------------------------------------------
template<int CIB>
__global__ __launch_bounds__(256, 2)
void mconv1(const ush* __restrict__ ah, const ush* __restrict__ al,
            const ush* __restrict__ ah2, const ush* __restrict__ al2, int cib1,
            const ush* __restrict__ wh, const ush* __restrict__ wl,
            const float* __restrict__ bias, float* __restrict__ outw,
            ush* __restrict__ xoh, ush* __restrict__ xol)
{
    constexpr int SROWS = 4, SCOLS = 66;
    constexpr int SLOTS = SROWS * SCOLS;          // 264
    constexpr int SLAB  = SLOTS * 128;            // 33792 bytes per hi slab
    constexpr int W_OFF = 2 * SLAB;               // 67584
    constexpr int WBUF  = 16384;                  // hi 8K + lo 8K per buffer
    constexpr int NG    = CIB * 18;               // (cib, tap, half) steps

    extern __shared__ __align__(16) char sm[];
    float* sbias = (float*)(sm + W_OFF + 2 * WBUF);

    const int tid  = threadIdx.x;
    const int lane = tid & 31, wid = tid >> 5;
    const int wm = wid >> 2, wn = wid & 3;
    const int b = blockIdx.z, y0 = blockIdx.x * 2;

    if (tid < 128) sbias[tid] = bias[tid];

    const int CI1 = cib1 * 64, CI2 = CIB * 64 - CI1;
    const u32 sSlab = smem_u32(sm);
    const u32 sWb   = smem_u32(sm + W_OFF);

    float acc[4][4][4];
#pragma unroll
    for (int mt = 0; mt < 4; mt++)
#pragma unroll
        for (int nt = 0; nt < 4; nt++)
#pragma unroll
            for (int r = 0; r < 4; r++) acc[mt][nt][r] = 0.f;

    // ---- A slab fill (full 64ci of cib) via cp.async ----
    auto fillA = [&](int cib) {
        const bool first = (cib < cib1);
        const ush* sh = first ? ah : ah2;
        const ush* sl = first ? al : al2;
        const int cstride = first ? CI1 : CI2;
        const int coff = first ? cib * 64 : cib * 64 - CI1;
        for (int i = tid; i < SLOTS; i += 256) {
            const int sr = i / SCOLS, sc = i - sr * SCOLS;
            const int y = y0 + sr - 1, x = sc - 1;
            const bool ok = ((unsigned)y < HH) & ((unsigned)x < WW);
            const int yc = ok ? y : 0, xc = ok ? x : 0;
            const size_t po = ((size_t)b * PP + yc * WW + xc) * (size_t)cstride + coff;
            const char* ph = (const char*)(sh + po);
            const char* pl = (const char*)(sl + po);
            const u32 dhi = sSlab + (u32)i * 128;
            const u32 sz = ok ? 16u : 0u;
#pragma unroll
            for (int j = 0; j < 8; j++) {
                const u32 off = ((u32)(j ^ (sc & 7))) << 4;
                cpa16(dhi + off,        ph + j * 16, sz);
                cpa16(dhi + SLAB + off, pl + j * 16, sz);
            }
        }
    };
    // ---- W half-tap tile fill via cp.async ----
    auto fillW = [&](int g, int buf) {
        const int cib = g / 18, th = g - cib * 18;
        const int tap = th >> 1, half = th & 1;
        const int row = tid >> 1;
        const size_t src = ((size_t)(tap * CIB + cib) * 128 + row) * 64 + half * 32;
        const u32 dbase = sWb + buf * WBUF + row * 64;
#pragma unroll
        for (int k = 0; k < 2; k++) {
            const int j = (tid & 1) * 2 + k;
            const u32 off = ((u32)(j ^ ((row >> 1) & 3))) << 4;
            cpa16(dbase + off,        wh + src + j * 8, 16);
            cpa16(dbase + 8192 + off, wl + src + j * 8, 16);
        }
    };

    // prologue
    fillA(0);
    fillW(0, 0);
    cpa_commit();
    cpa_wait0();
    __syncthreads();

    int g = 0;
    for (int cib = 0; cib < CIB; cib++) {
        for (int th = 0; th < 18; th++, g++) {
            const int buf = g & 1;
            if (g + 1 < NG) { fillW(g + 1, buf ^ 1); cpa_commit(); }

            const int tap = th >> 1, half = th & 1;
            const int ky = tap / 3, kx = tap - ky * 3;
            const u32 wb = sWb + buf * WBUF;
#pragma unroll
            for (int kcl = 0; kcl < 2; kcl++) {
                const int kc = half * 2 + kcl;
                // W fragments
                u32 bh[4][2], bl[4][2];
#pragma unroll
                for (int ntp = 0; ntp < 2; ntp++) {
                    const int sel = lane >> 3;
                    const int row = wn * 32 + ntp * 16 + ((sel & 2) << 2) + (lane & 7);
                    const int j = kcl * 2 + (sel & 1);
                    const u32 ad = wb + row * 64 + (((u32)(j ^ ((row >> 1) & 3))) << 4);
                    u32 r[4];
                    ldm4(r, ad);
                    bh[ntp*2][0] = r[0]; bh[ntp*2][1] = r[1];
                    bh[ntp*2+1][0] = r[2]; bh[ntp*2+1][1] = r[3];
                    ldm4(r, ad + 8192);
                    bl[ntp*2][0] = r[0]; bl[ntp*2][1] = r[1];
                    bl[ntp*2+1][0] = r[2]; bl[ntp*2+1][1] = r[3];
                }
                // A fragments + mma
#pragma unroll
                for (int mt = 0; mt < 4; mt++) {
                    const int p = wm * 64 + mt * 16 + (lane & 15);
                    const int oy = p >> 6, ox = p & 63;
                    const int col = ox + kx, srow = oy + ky;
                    const int slot = srow * SCOLS + col;
                    const int ja = kc * 2 + (lane >> 4);
                    const u32 ao = sSlab + (u32)slot * 128 + (((u32)(ja ^ (col & 7))) << 4);
                    u32 ahr[4], alr[4];
                    ldm4(ahr, ao);
                    ldm4(alr, ao + SLAB);
#pragma unroll
                    for (int nt = 0; nt < 4; nt++) {
                        mma16816(acc[mt][nt], ahr, bh[nt][0], bh[nt][1]);   // hi*hi
                        mma16816(acc[mt][nt], ahr, bl[nt][0], bl[nt][1]);   // hi*lo
                        mma16816(acc[mt][nt], alr, bh[nt][0], bh[nt][1]);   // lo*hi
                    }
                }
            }

            cpa_wait0();
            __syncthreads();
        }
        if (cib + 1 < CIB) {
            fillA(cib + 1);
            cpa_commit();
            cpa_wait0();
            __syncthreads();
        }
    }

    // epilogue
    const int r0 = lane >> 2, cp_ = (lane & 3) * 2;
#pragma unroll
    for (int mt = 0; mt < 4; mt++) {
#pragma unroll
        for (int half = 0; half < 2; half++) {
            const int px = wm * 64 + mt * 16 + r0 + half * 8;
            const int y = y0 + (px >> 6), x = px & 63;
            const size_t nb = (((size_t)b * OCH) * HH + y) * WW + x;
            const size_t hb = ((size_t)b * PP + y * WW + x) * 128;
#pragma unroll
            for (int nt = 0; nt < 4; nt++) {
                const int oc = wn * 32 + nt * 8 + cp_;
                const float f0 = lrelu(acc[mt][nt][half * 2 + 0] + sbias[oc]);
                const float f1 = lrelu(acc[mt][nt][half * 2 + 1] + sbias[oc + 1]);
                if (outw) {
                    outw[nb + (size_t)oc * PP]       = f0;
                    outw[nb + (size_t)(oc + 1) * PP] = f1;
                }
                if (xoh) {
                    ush h0, l0, h1, l1;
                    bsplit(f0, h0, l0); bsplit(f1, h1, l1);
                    *(u32*)(xoh + hb + oc) = (u32)h0 | ((u32)h1 << 16);
                    *(u32*)(xol + hb + oc) = (u32)l0 | ((u32)l1 << 16);
                }
            }
        }
    }
}

// ---------------------------------------------------------------------------
// Stride-2 tensor conv: R14 structure unchanged (proven).
// ---------------------------------------------------------------------------
template<int CIB, int STRIDE>
__global__ __launch_bounds__(256, 2)
void mconv(const ush* __restrict__ ah, const ush* __restrict__ al,
           const ush* __restrict__ ah2, const ush* __restrict__ al2, int cib1,
           const ush* __restrict__ wh, const ush* __restrict__ wl,
           const float* __restrict__ bias, float* __restrict__ outw,
           ush* __restrict__ xoh, ush* __restrict__ xol)
{
    constexpr int OWO   = WW / STRIDE;
    constexpr int ROWS  = 128 / OWO;
    constexpr int PPO   = (HH / STRIDE) * OWO;
    constexpr int SROWS = STRIDE * (ROWS - 1) + 3;
    constexpr int SLOTS = SROWS * 68;
    constexpr int SLABH = SLOTS * 32;
    constexpr int W_OFF = 2 * SLABH;
    constexpr int NST   = 4 * CIB;
    constexpr int NG    = NST * 9;

    extern __shared__ __align__(16) char sm[];
    float* sbias = (float*)(sm + W_OFF + 16384);

    const int tid  = threadIdx.x;
    const int lane = tid & 31, wid = tid >> 5;
    const int wm = wid >> 2, wn = wid & 3;
    const int b = blockIdx.z, y0 = blockIdx.x * ROWS;

    if (tid < 128) sbias[tid] = bias[tid];

    const int CI1 = cib1 * 64, CI2 = CIB * 64 - CI1;
    const u32 sSlab = smem_u32(sm);
    const u32 sWb   = smem_u32(sm + W_OFF);

    auto xv = [](int c) -> u32 { return (u32)((c & 12) << 2); };

    float acc[4][4][4];
#pragma unroll
    for (int mt = 0; mt < 4; mt++)
#pragma unroll
        for (int nt = 0; nt < 4; nt++)
#pragma unroll
            for (int r = 0; r < 4; r++) acc[mt][nt][r] = 0.f;

    const uint4 z4 = make_uint4(0, 0, 0, 0);
    uint4 wvh, wvl;

    auto fillA = [&](int st) {
        const int cib = st >> 2, kc = st & 3;
        const int ci = cib * 64 + kc * 16;
        for (int i = tid; i < SLOTS; i += 256) {
            const int sr = i / 68, sc = i - sr * 68;
            if (sc >= 66) continue;
            const int y = STRIDE * y0 + sr - 1, x = sc - 1;
            const bool ok = ((unsigned)y < HH) & ((unsigned)x < WW);
            const ush *ph, *pl;
            if (ci < CI1) {
                size_t off = ((size_t)b * PP + y * WW + x) * (size_t)CI1 + ci;
                ph = ah + off; pl = al + off;
            } else {
                size_t off = ((size_t)b * PP + y * WW + x) * (size_t)CI2 + (ci - CI1);
                ph = ah2 + off; pl = al2 + off;
            }
            uint4 h0 = ok ? *(const uint4*)ph        : z4;
            uint4 h1 = ok ? *(const uint4*)(ph + 8)  : z4;
            uint4 l0 = ok ? *(const uint4*)pl        : z4;
            uint4 l1 = ok ? *(const uint4*)(pl + 8)  : z4;
            const u32 base = (u32)i * 32, xr = xv(sc);
            *(uint4*)(sm + ((base)      ^ xr))          = h0;
            *(uint4*)(sm + ((base + 16) ^ xr))          = h1;
            *(uint4*)(sm + SLABH + ((base)      ^ xr))  = l0;
            *(uint4*)(sm + SLABH + ((base + 16) ^ xr))  = l1;
        }
    };
    auto ldgW = [&](int g) {
        const int st = g / 9, tap = g - st * 9;
        const int cib = st >> 2, kc = st & 3;
        size_t off = ((size_t)(tap * CIB + cib) * 128 + (tid >> 1)) * 64
                   + kc * 16 + (tid & 1) * 8;
        wvh = *(const uint4*)(wh + off);
        wvl = *(const uint4*)(wl + off);
    };
    auto stsW = [&](int buf) {
        const int row = tid >> 1, cc = tid & 1;
        const int ch = cc ^ ((row >> 2) & 1);
        char* base = sm + W_OFF + buf * 8192 + row * 32 + ch * 16;
        *(uint4*)base          = wvh;
        *(uint4*)(base + 4096) = wvl;
    };

    fillA(0);
    ldgW(0); stsW(0);
    __syncthreads();

    int g = 0;
    for (int st = 0; st < NST; st++) {
        for (int tap = 0; tap < 9; tap++, g++) {
            const int buf = g & 1;
            if (g + 1 < NG) ldgW(g + 1);
            const int ky = tap / 3, kx = tap - ky * 3;

            u32 bh[4][2], bl[4][2];
            const u32 wbase = sWb + buf * 8192;
#pragma unroll
            for (int ntp = 0; ntp < 2; ntp++) {
                const int sel = lane >> 3;
                const int row = wn * 32 + ntp * 16 + ((sel & 2) << 2) + (lane & 7);
                const int ch = (sel & 1) ^ ((row >> 2) & 1);
                const u32 ad = wbase + row * 32 + ch * 16;
                u32 r[4];
                ldm4(r, ad);
                bh[ntp*2][0] = r[0]; bh[ntp*2][1] = r[1];
                bh[ntp*2+1][0] = r[2]; bh[ntp*2+1][1] = r[3];
                ldm4(r, ad + 4096);
                bl[ntp*2][0] = r[0]; bl[ntp*2][1] = r[1];
                bl[ntp*2+1][0] = r[2]; bl[ntp*2+1][1] = r[3];
            }

#pragma unroll
            for (int mt = 0; mt < 4; mt++) {
                const int p  = wm * 64 + mt * 16 + (lane & 15);
                const int oy = p / OWO, ox = p - oy * OWO;
                const int col = STRIDE * ox + kx;
                const int srow = STRIDE * oy + ky;
                const u32 byte = (u32)(srow * 68 + col) * 32 + (u32)(lane >> 4) * 16;
                const u32 ao = sSlab + (byte ^ xv(col));
                u32 ahr[4], alr[4];
                ldm4(ahr, ao);
                ldm4(alr, ao + SLABH);
#pragma unroll
                for (int nt = 0; nt < 4; nt++) {
                    mma16816(acc[mt][nt], ahr, bh[nt][0], bh[nt][1]);
                    mma16816(acc[mt][nt], ahr, bl[nt][0], bl[nt][1]);
                    mma16816(acc[mt][nt], alr, bh[nt][0], bh[nt][1]);
                }
            }

            if (g + 1 < NG) stsW(buf ^ 1);
            __syncthreads();
        }
        if (st + 1 < NST) { fillA(st + 1); __syncthreads(); }
    }

    const int r0 = lane >> 2, cp_ = (lane & 3) * 2;
#pragma unroll
    for (int mt = 0; mt < 4; mt++) {
#pragma unroll
        for (int half = 0; half < 2; half++) {
            const int px = wm * 64 + mt * 16 + r0 + half * 8;
            const int y = y0 + px / OWO, x = px % OWO;
            const size_t nb = (((size_t)b * OCH) * (size_t)(HH / STRIDE) + y) * OWO + x;
#pragma unroll
            for (int nt = 0; nt < 4; nt++) {
                const int oc = wn * 32 + nt * 8 + cp_;
                const float f0 = lrelu(acc[mt][nt][half * 2 + 0] + sbias[oc]);
                const float f1 = lrelu(acc[mt][nt][half * 2 + 1] + sbias[oc + 1]);
                outw[nb + (size_t)oc * PPO]       = f0;
                outw[nb + (size_t)(oc + 1) * PPO] = f1;
            }
        }
    }
}

// ---------------------------------------------------------------------------
// Attention softmax (unchanged)
// ---------------------------------------------------------------------------
__global__ void attn_kernel(const float* __restrict__ out1,
                            const float* __restrict__ lin_w,
                            const float* __restrict__ lin_b,
                            float* __restrict__ attn)
{
    const int b = blockIdx.x, tid = threadIdx.x;
    const float* xb = out1 + (size_t)b * CIN * PP;
    float logit[16], lmax = -1e30f;
#pragma unroll
    for (int i = 0; i < 16; i++) {
        const int p = tid + i * 256;
        float acc = lin_b[p];
        const float4* wr = (const float4*)(lin_w + (size_t)p * CIN);
#pragma unroll
        for (int c4 = 0; c4 < CIN / 4; c4++) {
            float4 w4 = wr[c4];
            acc = fmaf(w4.x, xb[(c4*4+0)*PP + p], acc);
            acc = fmaf(w4.y, xb[(c4*4+1)*PP + p], acc);
            acc = fmaf(w4.z, xb[(c4*4+2)*PP + p], acc);
            acc = fmaf(w4.w, xb[(c4*4+3)*PP + p], acc);
        }
        logit[i] = acc; lmax = fmaxf(lmax, acc);
    }
    __shared__ float red[256];
    red[tid] = lmax; __syncthreads();
    for (int s = 128; s > 0; s >>= 1) { if (tid < s) red[tid] = fmaxf(red[tid], red[tid+s]); __syncthreads(); }
    const float m = red[0]; __syncthreads();
    float lsum = 0.f;
#pragma unroll
    for (int i = 0; i < 16; i++) { logit[i] = expf(logit[i] - m); lsum += logit[i]; }
    red[tid] = lsum; __syncthreads();
    for (int s = 128; s > 0; s >>= 1) { if (tid < s) red[tid] += red[tid+s]; __syncthreads(); }
    const float inv = 1.0f / red[0];
#pragma unroll
    for (int i = 0; i < 16; i++) attn[(size_t)b * PP + tid + i*256] = logit[i] * inv;
}

// ---------------------------------------------------------------------------
__global__ void bo3_kernel(const float* __restrict__ prev,
                           const float* __restrict__ attn,
                           float* __restrict__ out)
{
    const int idx = blockIdx.x * 256 + threadIdx.x;
    const int ox = idx & 31, oy = (idx >> 5) & 31, bc = idx >> 10;
    const int b = bc >> 7;
    const float* pv = prev + (size_t)bc * PP;
    const float* at = attn + (size_t)b * PP;
    const float BIN = 63.0f / 32.0f;
    float acc = 0.f;
#pragma unroll
    for (int sy = 0; sy < 2; sy++) {
        const float ys = ((float)oy + 0.25f + 0.5f * sy) * BIN;
        const int y0 = (int)ys, y1 = min(y0 + 1, HH - 1);
        const float ly = ys - (float)y0, hy = 1.f - ly;
#pragma unroll
        for (int sx = 0; sx < 2; sx++) {
            const float xs = ((float)ox + 0.25f + 0.5f * sx) * BIN;
            const int x0 = (int)xs, x1 = min(x0 + 1, WW - 1);
            const float lx = xs - (float)x0, hx = 1.f - lx;
            const float f00 = pv[y0*WW+x0]*at[y0*WW+x0], f01 = pv[y0*WW+x1]*at[y0*WW+x1];
            const float f10 = pv[y1*WW+x0]*at[y1*WW+x0], f11 = pv[y1*WW+x1]*at[y1*WW+x1];
            acc += hy * (hx*f00 + lx*f01) + ly * (hx*f10 + lx*f11);
        }
    }
    out[idx] = acc * 0.25f;
}

__global__ void combine_kernel(const float* __restrict__ l2,
                               const float* __restrict__ aux,
                               float* __restrict__ out)
{
    const int idx = blockIdx.x * 256 + threadIdx.x;
    const int ox = idx & 31, oy = (idx >> 5) & 31, bc = idx >> 10;
    const float* src = l2 + (size_t)bc * PP;
    const float BIN = 63.0f / 32.0f;
    float acc = 0.f;
#pragma unroll
    for (int sy = 0; sy < 2; sy++) {
        const float ys = ((float)oy + 0.25f + 0.5f * sy) * BIN;
        const int y0 = (int)ys, y1 = min(y0 + 1, HH - 1);
        const float ly = ys - (float)y0, hy = 1.f - ly;
#pragma unroll
        for (int sx = 0; sx < 2; sx++) {
            const float xs = ((float)ox + 0.25f + 0.5f * sx) * BIN;
            const int x0 = (int)xs, x1 = min(x0 + 1, WW - 1);
            const float lx = xs - (float)x0, hx = 1.f - lx;
            acc += hy * (hx*src[y0*WW+x0] + lx*src[y0*WW+x1])
                 + ly * (hx*src[y1*WW+x0] + lx*src[y1*WW+x1]);
        }
    }
    out[idx] = acc * 0.25f + aux[idx] + out[SLICE + idx] + out[2*SLICE + idx];
}

// ---------------------------------------------------------------------------
extern "C" void kernel_launch(void* const* d_in, const int* in_sizes, int n_in,
                              void* d_out, int out_size)
{
    const float* out1   = (const float*)d_in[0];
    const float* out2   = (const float*)d_in[1];
    const float* out3   = (const float*)d_in[2];
    const float* w1     = (const float*)d_in[3];
    const float* b1     = (const float*)d_in[4];
    const float* w2     = (const float*)d_in[5];
    const float* b2     = (const float*)d_in[6];
    const float* w3     = (const float*)d_in[7];
    const float* b3     = (const float*)d_in[8];
    const float* w_aux  = (const float*)d_in[9];
    const float* b_aux  = (const float*)d_in[10];
    const float* w_b2   = (const float*)d_in[11];
    const float* b_b2   = (const float*)d_in[12];
    const float* w_prev = (const float*)d_in[13];
    const float* b_prev = (const float*)d_in[14];
    const float* lin_w  = (const float*)d_in[15];
    const float* lin_b  = (const float*)d_in[16];
    float* out = (float*)d_out;

    float *l2, *prev, *aux, *attn;
    cudaGetSymbolAddress((void**)&l2,   g_l2);
    cudaGetSymbolAddress((void**)&prev, g_prev);
    cudaGetSymbolAddress((void**)&aux,  g_aux);
    cudaGetSymbolAddress((void**)&attn, g_attn);
    ush *x1h,*x1l,*x2h,*x2l,*x3h,*x3l,*x4h,*x4l,*xph,*xpl;
    ush *w1h,*w1l,*w2h,*w2l,*w3h,*w3l,*wph,*wpl,*wbh,*wbl,*wah,*wal;
    cudaGetSymbolAddress((void**)&x1h, g_x1h); cudaGetSymbolAddress((void**)&x1l, g_x1l);
    cudaGetSymbolAddress((void**)&x2h, g_x2h); cudaGetSymbolAddress((void**)&x2l, g_x2l);
    cudaGetSymbolAddress((void**)&x3h, g_x3h); cudaGetSymbolAddress((void**)&x3l, g_x3l);
    cudaGetSymbolAddress((void**)&x4h, g_x4h); cudaGetSymbolAddress((void**)&x4l, g_x4l);
    cudaGetSymbolAddress((void**)&xph, g_xph); cudaGetSymbolAddress((void**)&xpl, g_xpl);
    cudaGetSymbolAddress((void**)&w1h, g_w1h); cudaGetSymbolAddress((void**)&w1l, g_w1l);
    cudaGetSymbolAddress((void**)&w2h, g_w2h); cudaGetSymbolAddress((void**)&w2l, g_w2l);
    cudaGetSymbolAddress((void**)&w3h, g_w3h); cudaGetSymbolAddress((void**)&w3l, g_w3l);
    cudaGetSymbolAddress((void**)&wph, g_wph); cudaGetSymbolAddress((void**)&wpl, g_wpl);
    cudaGetSymbolAddress((void**)&wbh, g_wbh); cudaGetSymbolAddress((void**)&wbl, g_wbl);
    cudaGetSymbolAddress((void**)&wah, g_wah); cudaGetSymbolAddress((void**)&wal, g_wal);

    static cudaStream_t sB = nullptr, sC = nullptr;
    static cudaEvent_t eFork = nullptr, eL2 = nullptr, eB = nullptr, eC = nullptr, eW = nullptr;
    if (!sB) {
        cudaStreamCreateWithFlags(&sB, cudaStreamNonBlocking);
        cudaStreamCreateWithFlags(&sC, cudaStreamNonBlocking);
        cudaEventCreateWithFlags(&eFork, cudaEventDisableTiming);
        cudaEventCreateWithFlags(&eL2,   cudaEventDisableTiming);
        cudaEventCreateWithFlags(&eB,    cudaEventDisableTiming);
        cudaEventCreateWithFlags(&eC,    cudaEventDisableTiming);
        cudaEventCreateWithFlags(&eW,    cudaEventDisableTiming);
    }

    // dynamic smem
    const int smem_m1 = 2 * (264 * 128) + 2 * 16384 + 512;   // 100352+512 = 100864... slab 67584 + 32768 + 512 = 100864
    const int smem_s2 = 2 * (9 * 68 * 32) + 16384 + 512;     // 56064
    cudaFuncSetAttribute(mconv1<1>, cudaFuncAttributeMaxDynamicSharedMemorySize, smem_m1);
    cudaFuncSetAttribute(mconv1<2>, cudaFuncAttributeMaxDynamicSharedMemorySize, smem_m1);
    cudaFuncSetAttribute(mconv<2,2>, cudaFuncAttributeMaxDynamicSharedMemorySize, smem_s2);
    cudaFuncSetAttribute(mconv<4,2>, cudaFuncAttributeMaxDynamicSharedMemorySize, smem_s2);

    const dim3 gsM1(32, 1, 32);      // stride-1 tensor convs
    const dim3 gsM2(8, 1, 32);       // stride-2 tensor convs
    const dim3 gsA(64, 32);          // asplit
    const int  nPix = (int)(SLICE / 256);

    cudaEventRecord(eFork, 0);
    cudaStreamWaitEvent(sB, eFork, 0);
    cudaStreamWaitEvent(sC, eFork, 0);

    // ---- stream B: attn + prev chain + bo3 ----
    attn_kernel<<<BB, 256, 0, sB>>>(out1, lin_w, lin_b, attn);
    wsplit<<<(128*128*9 + 255)/256, 256, 0, sB>>>(w_prev, 128, wph, wpl);
    asplit<128><<<gsA, 256, 0, sB>>>(out2, out3, 64, xph, xpl);
    mconv1<2><<<gsM1, 256, smem_m1, sB>>>(xph, xpl, xph, xpl, 2, wph, wpl, b_prev,
                                          prev, nullptr, nullptr);
    bo3_kernel<<<nPix, 256, 0, sB>>>(prev, attn, out + 2*SLICE);
    cudaEventRecord(eB, sB);

    // ---- stream C: weight preps off critical path ----
    wsplit<<<(128*128*9 + 255)/256, 256, 0, sC>>>(w2, 128, w2h, w2l);
    wsplit<<<(128*128*9 + 255)/256, 256, 0, sC>>>(w3, 128, w3h, w3l);
    wsplit<<<(128*128*9 + 255)/256, 256, 0, sC>>>(w_aux, 128, wah, wal);
    wsplit<<<(128*256*9 + 255)/256, 256, 0, sC>>>(w_b2, 256, wbh, wbl);
    cudaEventRecord(eW, sC);

    // ---- main chain ----
    wsplit<<<(128*64*9 + 255)/256, 256>>>(w1, 64, w1h, w1l);
    asplit<64><<<gsA, 256>>>(out1, nullptr, 64, x1h, x1l);
    mconv1<1><<<gsM1, 256, smem_m1>>>(x1h, x1l, x1h, x1l, 1, w1h, w1l, b1,
                                      nullptr, x2h, x2l);               // l1 (HWC only)
    cudaStreamWaitEvent(0, eW, 0);
    mconv1<2><<<gsM1, 256, smem_m1>>>(x2h, x2l, x2h, x2l, 2, w2h, w2l, b2,
                                      l2, x3h, x3l);                    // l2

    cudaEventRecord(eL2, 0);
    cudaStreamWaitEvent(sC, eL2, 0);
    mconv<4,2><<<gsM2, 256, smem_s2, sC>>>(x2h, x2l, x3h, x3l, 2, wbh, wbl, b_b2,
                                           out + SLICE, nullptr, nullptr);  // block_out2
    cudaEventRecord(eC, sC);

    mconv1<2><<<gsM1, 256, smem_m1>>>(x3h, x3l, x3h, x3l, 2, w3h, w3l, b3,
                                      nullptr, x4h, x4l);               // l3 (HWC only)
    mconv<2,2><<<gsM2, 256, smem_s2>>>(x4h, x4l, x4h, x4l, 2, wah, wal, b_aux,
                                       aux, nullptr, nullptr);          // aux

    cudaStreamWaitEvent(0, eB, 0);
    cudaStreamWaitEvent(0, eC, 0);
    combine_kernel<<<nPix, 256>>>(l2, aux, out);
}

// round 17
// speedup vs baseline: 3.1991x; 1.0080x over previous
#include <cuda_runtime.h>

#define BB   32
#define CIN  64
#define OCH  128
#define HH   64
#define WW   64
#define PP   (HH*WW)
#define OH   32
#define OW   32
#define SLICE ((size_t)BB*OCH*OH*OW)

typedef unsigned long long u64;
typedef unsigned int u32;
typedef unsigned short ush;

// ---------------- scratch (device globals) ----------------
__device__ float g_l2  [BB*OCH*HH*WW];
__device__ float g_prev[BB*OCH*HH*WW];
__device__ float g_aux [BB*OCH*OH*OW];
__device__ float g_attn[BB*PP];
// HWC bf16 hi/lo activation buffers
__device__ ush g_x1h[BB*PP*64],  g_x1l[BB*PP*64];     // out1
__device__ ush g_x2h[BB*PP*128], g_x2l[BB*PP*128];    // l1
__device__ ush g_x3h[BB*PP*128], g_x3l[BB*PP*128];    // l2
__device__ ush g_x4h[BB*PP*128], g_x4l[BB*PP*128];    // l3
__device__ ush g_xph[BB*PP*128], g_xpl[BB*PP*128];    // concat(out2,out3)
// weight B-tiles: [tap][cib][128 oc][64 ci]
__device__ ush g_w1h[9*1*128*64], g_w1l[9*1*128*64];
__device__ ush g_w2h[9*2*128*64], g_w2l[9*2*128*64];
__device__ ush g_w3h[9*2*128*64], g_w3l[9*2*128*64];
__device__ ush g_wph[9*2*128*64], g_wpl[9*2*128*64];
__device__ ush g_wbh[9*4*128*64], g_wbl[9*4*128*64];  // w_b2 (CI=256)
__device__ ush g_wah[9*2*128*64], g_wal[9*2*128*64];  // w_aux

__device__ __forceinline__ float lrelu(float x) { return x >= 0.f ? x : 0.1f * x; }

// ---- bf16 split ----
__device__ __forceinline__ u32 bf16rn(float x) {
    u32 u = __float_as_uint(x);
    return (u + 0x7FFFu + ((u >> 16) & 1u)) >> 16;
}
__device__ __forceinline__ void bsplit(float x, ush& h, ush& l) {
    u32 uh = bf16rn(x); h = (ush)uh;
    float fh = __uint_as_float(uh << 16);
    l = (ush)bf16rn(x - fh);
}

__device__ __forceinline__ u32 smem_u32(const void* p) {
    u32 a; asm("{ .reg .u64 t; cvta.to.shared.u64 t, %1; cvt.u32.u64 %0, t; }" : "=r"(a) : "l"(p));
    return a;
}
// ldmatrix x4 (sm_75+ baseline PTX)
__device__ __forceinline__ void ldm4(u32* r, u32 a) {
    asm volatile("ldmatrix.sync.aligned.m8n8.x4.shared.b16 {%0,%1,%2,%3}, [%4];"
        : "=r"(r[0]), "=r"(r[1]), "=r"(r[2]), "=r"(r[3]) : "r"(a));
}
// mma.sync bf16 (sm_80+ baseline PTX) -> HMMA on Blackwell
__device__ __forceinline__ void mma16816(float* c, const u32* a, u32 b0, u32 b1) {
    asm volatile("mma.sync.aligned.m16n8k16.row.col.f32.bf16.bf16.f32 "
        "{%0,%1,%2,%3}, {%4,%5,%6,%7}, {%8,%9}, {%0,%1,%2,%3};"
        : "+f"(c[0]), "+f"(c[1]), "+f"(c[2]), "+f"(c[3])
        : "r"(a[0]), "r"(a[1]), "r"(a[2]), "r"(a[3]), "r"(b0), "r"(b1));
}
// cp.async 16B (sm_80+ baseline PTX); src_size<16 zero-fills remainder
__device__ __forceinline__ void cpa16(u32 dst, const void* src, u32 sz) {
    asm volatile("cp.async.cg.shared.global [%0], [%1], 16, %2;"
        :: "r"(dst), "l"(src), "r"(sz) : "memory");
}
__device__ __forceinline__ void cpa_commit() {
    asm volatile("cp.async.commit_group;" ::: "memory");
}
__device__ __forceinline__ void cpa_wait0() {
    asm volatile("cp.async.wait_group 0;" ::: "memory");
}

// ---------------------------------------------------------------------------
// Prep: NCHW fp32 (optionally concat of two) -> HWC bf16 hi/lo
// ---------------------------------------------------------------------------
template<int CI>
__global__ __launch_bounds__(256)
void asplit(const float* __restrict__ s0, const float* __restrict__ s1, int csplit,
            ush* __restrict__ oh, ush* __restrict__ ol)
{
    __shared__ float t[CI][65];
    const int b = blockIdx.y, p0 = blockIdx.x * 64;
    for (int f = threadIdx.x; f < CI * 16; f += 256) {
        int ci = f >> 4, c4 = (f & 15) * 4;
        const float* src = (ci < csplit)
            ? s0 + ((size_t)b * csplit + ci) * PP
            : s1 + ((size_t)b * (CI - csplit) + ci - csplit) * PP;
        float4 v = *(const float4*)(src + p0 + c4);
        t[ci][c4] = v.x; t[ci][c4+1] = v.y; t[ci][c4+2] = v.z; t[ci][c4+3] = v.w;
    }
    __syncthreads();
    for (int cid = threadIdx.x; cid < 64 * (CI / 8); cid += 256) {
        int px = cid / (CI / 8), k8 = cid % (CI / 8);
        u32 hu[4], lu[4];
#pragma unroll
        for (int j = 0; j < 4; j++) {
            ush h0, l0, h1, l1;
            bsplit(t[k8*8 + 2*j][px],     h0, l0);
            bsplit(t[k8*8 + 2*j + 1][px], h1, l1);
            hu[j] = (u32)h0 | ((u32)h1 << 16);
            lu[j] = (u32)l0 | ((u32)l1 << 16);
        }
        size_t off = ((size_t)b * PP + p0 + px) * CI + k8 * 8;
        *(uint4*)(oh + off) = *(uint4*)hu;
        *(uint4*)(ol + off) = *(uint4*)lu;
    }
}

// Prep: weights [128][CI][3][3] fp32 -> [tap][cib][128][64] bf16 hi/lo
__global__ void wsplit(const float* __restrict__ w, int CI,
                       ush* __restrict__ oh, ush* __restrict__ ol)
{
    int i = blockIdx.x * 256 + threadIdx.x;
    if (i >= 128 * CI * 9) return;
    int oc = i / (CI * 9), r = i % (CI * 9), ci = r / 9, tap = r % 9;
    ush h, l; bsplit(w[i], h, l);
    size_t o = (((size_t)(tap * (CI >> 6) + (ci >> 6)) * 128 + oc) * 64 + (ci & 63));
    oh[o] = h; ol[o] = l;
}

// ---------------------------------------------------------------------------
// Stride-1 tensor conv. A slab (full 64ci per cib) via cp.async; W dbuf via
// cp.async. Inner mma stream PRODUCT-MAJOR: same-acc reuse distance 1 -> 4.
// CTA: 256 thr (8 warps 2x4); D = 128 px x 128 oc in registers.
// ---------------------------------------------------------------------------
template<int CIB>
__global__ __launch_bounds__(256, 2)
void mconv1(const ush* __restrict__ ah, const ush* __restrict__ al,
            const ush* __restrict__ ah2, const ush* __restrict__ al2, int cib1,
            const ush* __restrict__ wh, const ush* __restrict__ wl,
            const float* __restrict__ bias, float* __restrict__ outw,
            ush* __restrict__ xoh, ush* __restrict__ xol)
{
    constexpr int SROWS = 4, SCOLS = 66;
    constexpr int SLOTS = SROWS * SCOLS;          // 264
    constexpr int SLAB  = SLOTS * 128;            // 33792 bytes per hi slab
    constexpr int W_OFF = 2 * SLAB;               // 67584
    constexpr int WBUF  = 16384;                  // hi 8K + lo 8K per buffer
    constexpr int NG    = CIB * 18;               // (cib, tap, half) steps

    extern __shared__ __align__(16) char sm[];
    float* sbias = (float*)(sm + W_OFF + 2 * WBUF);

    const int tid  = threadIdx.x;
    const int lane = tid & 31, wid = tid >> 5;
    const int wm = wid >> 2, wn = wid & 3;
    const int b = blockIdx.z, y0 = blockIdx.x * 2;

    if (tid < 128) sbias[tid] = bias[tid];

    const int CI1 = cib1 * 64, CI2 = CIB * 64 - CI1;
    const u32 sSlab = smem_u32(sm);
    const u32 sWb   = smem_u32(sm + W_OFF);

    float acc[4][4][4];
#pragma unroll
    for (int mt = 0; mt < 4; mt++)
#pragma unroll
        for (int nt = 0; nt < 4; nt++)
#pragma unroll
            for (int r = 0; r < 4; r++) acc[mt][nt][r] = 0.f;

    // ---- A slab fill (full 64ci of cib) via cp.async ----
    auto fillA = [&](int cib) {
        const bool first = (cib < cib1);
        const ush* sh = first ? ah : ah2;
        const ush* sl = first ? al : al2;
        const int cstride = first ? CI1 : CI2;
        const int coff = first ? cib * 64 : cib * 64 - CI1;
        for (int i = tid; i < SLOTS; i += 256) {
            const int sr = i / SCOLS, sc = i - sr * SCOLS;
            const int y = y0 + sr - 1, x = sc - 1;
            const bool ok = ((unsigned)y < HH) & ((unsigned)x < WW);
            const int yc = ok ? y : 0, xc = ok ? x : 0;
            const size_t po = ((size_t)b * PP + yc * WW + xc) * (size_t)cstride + coff;
            const char* ph = (const char*)(sh + po);
            const char* pl = (const char*)(sl + po);
            const u32 dhi = sSlab + (u32)i * 128;
            const u32 sz = ok ? 16u : 0u;
#pragma unroll
            for (int j = 0; j < 8; j++) {
                const u32 off = ((u32)(j ^ (sc & 7))) << 4;
                cpa16(dhi + off,        ph + j * 16, sz);
                cpa16(dhi + SLAB + off, pl + j * 16, sz);
            }
        }
    };
    // ---- W half-tap tile fill via cp.async ----
    auto fillW = [&](int g, int buf) {
        const int cib = g / 18, th = g - cib * 18;
        const int tap = th >> 1, half = th & 1;
        const int row = tid >> 1;
        const size_t src = ((size_t)(tap * CIB + cib) * 128 + row) * 64 + half * 32;
        const u32 dbase = sWb + buf * WBUF + row * 64;
#pragma unroll
        for (int k = 0; k < 2; k++) {
            const int j = (tid & 1) * 2 + k;
            const u32 off = ((u32)(j ^ ((row >> 1) & 3))) << 4;
            cpa16(dbase + off,        wh + src + j * 8, 16);
            cpa16(dbase + 8192 + off, wl + src + j * 8, 16);
        }
    };

    // prologue
    fillA(0);
    fillW(0, 0);
    cpa_commit();
    cpa_wait0();
    __syncthreads();

    int g = 0;
    for (int cib = 0; cib < CIB; cib++) {
        for (int th = 0; th < 18; th++, g++) {
            const int buf = g & 1;
            if (g + 1 < NG) { fillW(g + 1, buf ^ 1); cpa_commit(); }

            const int tap = th >> 1, half = th & 1;
            const int ky = tap / 3, kx = tap - ky * 3;
            const u32 wb = sWb + buf * WBUF;
#pragma unroll
            for (int kcl = 0; kcl < 2; kcl++) {
                const int kc = half * 2 + kcl;
                // W fragments
                u32 bh[4][2], bl[4][2];
#pragma unroll
                for (int ntp = 0; ntp < 2; ntp++) {
                    const int sel = lane >> 3;
                    const int row = wn * 32 + ntp * 16 + ((sel & 2) << 2) + (lane & 7);
                    const int j = kcl * 2 + (sel & 1);
                    const u32 ad = wb + row * 64 + (((u32)(j ^ ((row >> 1) & 3))) << 4);
                    u32 r[4];
                    ldm4(r, ad);
                    bh[ntp*2][0] = r[0]; bh[ntp*2][1] = r[1];
                    bh[ntp*2+1][0] = r[2]; bh[ntp*2+1][1] = r[3];
                    ldm4(r, ad + 8192);
                    bl[ntp*2][0] = r[0]; bl[ntp*2][1] = r[1];
                    bl[ntp*2+1][0] = r[2]; bl[ntp*2+1][1] = r[3];
                }
                // A fragments + mma (PRODUCT-MAJOR: acc reuse distance = 4)
#pragma unroll
                for (int mt = 0; mt < 4; mt++) {
                    const int p = wm * 64 + mt * 16 + (lane & 15);
                    const int oy = p >> 6, ox = p & 63;
                    const int col = ox + kx, srow = oy + ky;
                    const int slot = srow * SCOLS + col;
                    const int ja = kc * 2 + (lane >> 4);
                    const u32 ao = sSlab + (u32)slot * 128 + (((u32)(ja ^ (col & 7))) << 4);
                    u32 ahr[4], alr[4];
                    ldm4(ahr, ao);
                    ldm4(alr, ao + SLAB);
#pragma unroll
                    for (int nt = 0; nt < 4; nt++)
                        mma16816(acc[mt][nt], ahr, bh[nt][0], bh[nt][1]);   // hi*hi
#pragma unroll
                    for (int nt = 0; nt < 4; nt++)
                        mma16816(acc[mt][nt], ahr, bl[nt][0], bl[nt][1]);   // hi*lo
#pragma unroll
                    for (int nt = 0; nt < 4; nt++)
                        mma16816(acc[mt][nt], alr, bh[nt][0], bh[nt][1]);   // lo*hi
                }
            }

            cpa_wait0();
            __syncthreads();
        }
        if (cib + 1 < CIB) {
            fillA(cib + 1);
            cpa_commit();
            cpa_wait0();
            __syncthreads();
        }
    }

    // epilogue
    const int r0 = lane >> 2, cp_ = (lane & 3) * 2;
#pragma unroll
    for (int mt = 0; mt < 4; mt++) {
#pragma unroll
        for (int half = 0; half < 2; half++) {
            const int px = wm * 64 + mt * 16 + r0 + half * 8;
            const int y = y0 + (px >> 6), x = px & 63;
            const size_t nb = (((size_t)b * OCH) * HH + y) * WW + x;
            const size_t hb = ((size_t)b * PP + y * WW + x) * 128;
#pragma unroll
            for (int nt = 0; nt < 4; nt++) {
                const int oc = wn * 32 + nt * 8 + cp_;
                const float f0 = lrelu(acc[mt][nt][half * 2 + 0] + sbias[oc]);
                const float f1 = lrelu(acc[mt][nt][half * 2 + 1] + sbias[oc + 1]);
                if (outw) {
                    outw[nb + (size_t)oc * PP]       = f0;
                    outw[nb + (size_t)(oc + 1) * PP] = f1;
                }
                if (xoh) {
                    ush h0, l0, h1, l1;
                    bsplit(f0, h0, l0); bsplit(f1, h1, l1);
                    *(u32*)(xoh + hb + oc) = (u32)h0 | ((u32)h1 << 16);
                    *(u32*)(xol + hb + oc) = (u32)l0 | ((u32)l1 << 16);
                }
            }
        }
    }
}

// ---------------------------------------------------------------------------
// Stride-2 tensor conv (R14 structure), mma stream product-major.
// ---------------------------------------------------------------------------
template<int CIB, int STRIDE>
__global__ __launch_bounds__(256, 2)
void mconv(const ush* __restrict__ ah, const ush* __restrict__ al,
           const ush* __restrict__ ah2, const ush* __restrict__ al2, int cib1,
           const ush* __restrict__ wh, const ush* __restrict__ wl,
           const float* __restrict__ bias, float* __restrict__ outw,
           ush* __restrict__ xoh, ush* __restrict__ xol)
{
    constexpr int OWO   = WW / STRIDE;
    constexpr int ROWS  = 128 / OWO;
    constexpr int PPO   = (HH / STRIDE) * OWO;
    constexpr int SROWS = STRIDE * (ROWS - 1) + 3;
    constexpr int SLOTS = SROWS * 68;
    constexpr int SLABH = SLOTS * 32;
    constexpr int W_OFF = 2 * SLABH;
    constexpr int NST   = 4 * CIB;
    constexpr int NG    = NST * 9;

    extern __shared__ __align__(16) char sm[];
    float* sbias = (float*)(sm + W_OFF + 16384);

    const int tid  = threadIdx.x;
    const int lane = tid & 31, wid = tid >> 5;
    const int wm = wid >> 2, wn = wid & 3;
    const int b = blockIdx.z, y0 = blockIdx.x * ROWS;

    if (tid < 128) sbias[tid] = bias[tid];

    const int CI1 = cib1 * 64, CI2 = CIB * 64 - CI1;
    const u32 sSlab = smem_u32(sm);
    const u32 sWb   = smem_u32(sm + W_OFF);

    auto xv = [](int c) -> u32 { return (u32)((c & 12) << 2); };

    float acc[4][4][4];
#pragma unroll
    for (int mt = 0; mt < 4; mt++)
#pragma unroll
        for (int nt = 0; nt < 4; nt++)
#pragma unroll
            for (int r = 0; r < 4; r++) acc[mt][nt][r] = 0.f;

    const uint4 z4 = make_uint4(0, 0, 0, 0);
    uint4 wvh, wvl;

    auto fillA = [&](int st) {
        const int cib = st >> 2, kc = st & 3;
        const int ci = cib * 64 + kc * 16;
        for (int i = tid; i < SLOTS; i += 256) {
            const int sr = i / 68, sc = i - sr * 68;
            if (sc >= 66) continue;
            const int y = STRIDE * y0 + sr - 1, x = sc - 1;
            const bool ok = ((unsigned)y < HH) & ((unsigned)x < WW);
            const ush *ph, *pl;
            if (ci < CI1) {
                size_t off = ((size_t)b * PP + y * WW + x) * (size_t)CI1 + ci;
                ph = ah + off; pl = al + off;
            } else {
                size_t off = ((size_t)b * PP + y * WW + x) * (size_t)CI2 + (ci - CI1);
                ph = ah2 + off; pl = al2 + off;
            }
            uint4 h0 = ok ? *(const uint4*)ph        : z4;
            uint4 h1 = ok ? *(const uint4*)(ph + 8)  : z4;
            uint4 l0 = ok ? *(const uint4*)pl        : z4;
            uint4 l1 = ok ? *(const uint4*)(pl + 8)  : z4;
            const u32 base = (u32)i * 32, xr = xv(sc);
            *(uint4*)(sm + ((base)      ^ xr))          = h0;
            *(uint4*)(sm + ((base + 16) ^ xr))          = h1;
            *(uint4*)(sm + SLABH + ((base)      ^ xr))  = l0;
            *(uint4*)(sm + SLABH + ((base + 16) ^ xr))  = l1;
        }
    };
    auto ldgW = [&](int g) {
        const int st = g / 9, tap = g - st * 9;
        const int cib = st >> 2, kc = st & 3;
        size_t off = ((size_t)(tap * CIB + cib) * 128 + (tid >> 1)) * 64
                   + kc * 16 + (tid & 1) * 8;
        wvh = *(const uint4*)(wh + off);
        wvl = *(const uint4*)(wl + off);
    };
    auto stsW = [&](int buf) {
        const int row = tid >> 1, cc = tid & 1;
        const int ch = cc ^ ((row >> 2) & 1);
        char* base = sm + W_OFF + buf * 8192 + row * 32 + ch * 16;
        *(uint4*)base          = wvh;
        *(uint4*)(base + 4096) = wvl;
    };

    fillA(0);
    ldgW(0); stsW(0);
    __syncthreads();

    int g = 0;
    for (int st = 0; st < NST; st++) {
        for (int tap = 0; tap < 9; tap++, g++) {
            const int buf = g & 1;
            if (g + 1 < NG) ldgW(g + 1);
            const int ky = tap / 3, kx = tap - ky * 3;

            u32 bh[4][2], bl[4][2];
            const u32 wbase = sWb + buf * 8192;
#pragma unroll
            for (int ntp = 0; ntp < 2; ntp++) {
                const int sel = lane >> 3;
                const int row = wn * 32 + ntp * 16 + ((sel & 2) << 2) + (lane & 7);
                const int ch = (sel & 1) ^ ((row >> 2) & 1);
                const u32 ad = wbase + row * 32 + ch * 16;
                u32 r[4];
                ldm4(r, ad);
                bh[ntp*2][0] = r[0]; bh[ntp*2][1] = r[1];
                bh[ntp*2+1][0] = r[2]; bh[ntp*2+1][1] = r[3];
                ldm4(r, ad + 4096);
                bl[ntp*2][0] = r[0]; bl[ntp*2][1] = r[1];
                bl[ntp*2+1][0] = r[2]; bl[ntp*2+1][1] = r[3];
            }

#pragma unroll
            for (int mt = 0; mt < 4; mt++) {
                const int p  = wm * 64 + mt * 16 + (lane & 15);
                const int oy = p / OWO, ox = p - oy * OWO;
                const int col = STRIDE * ox + kx;
                const int srow = STRIDE * oy + ky;
                const u32 byte = (u32)(srow * 68 + col) * 32 + (u32)(lane >> 4) * 16;
                const u32 ao = sSlab + (byte ^ xv(col));
                u32 ahr[4], alr[4];
                ldm4(ahr, ao);
                ldm4(alr, ao + SLABH);
#pragma unroll
                for (int nt = 0; nt < 4; nt++)
                    mma16816(acc[mt][nt], ahr, bh[nt][0], bh[nt][1]);   // hi*hi
#pragma unroll
                for (int nt = 0; nt < 4; nt++)
                    mma16816(acc[mt][nt], ahr, bl[nt][0], bl[nt][1]);   // hi*lo
#pragma unroll
                for (int nt = 0; nt < 4; nt++)
                    mma16816(acc[mt][nt], alr, bh[nt][0], bh[nt][1]);   // lo*hi
            }

            if (g + 1 < NG) stsW(buf ^ 1);
            __syncthreads();
        }
        if (st + 1 < NST) { fillA(st + 1); __syncthreads(); }
    }

    const int r0 = lane >> 2, cp_ = (lane & 3) * 2;
#pragma unroll
    for (int mt = 0; mt < 4; mt++) {
#pragma unroll
        for (int half = 0; half < 2; half++) {
            const int px = wm * 64 + mt * 16 + r0 + half * 8;
            const int y = y0 + px / OWO, x = px % OWO;
            const size_t nb = (((size_t)b * OCH) * (size_t)(HH / STRIDE) + y) * OWO + x;
#pragma unroll
            for (int nt = 0; nt < 4; nt++) {
                const int oc = wn * 32 + nt * 8 + cp_;
                const float f0 = lrelu(acc[mt][nt][half * 2 + 0] + sbias[oc]);
                const float f1 = lrelu(acc[mt][nt][half * 2 + 1] + sbias[oc + 1]);
                outw[nb + (size_t)oc * PPO]       = f0;
                outw[nb + (size_t)(oc + 1) * PPO] = f1;
            }
        }
    }
}

// ---------------------------------------------------------------------------
// Attention softmax (unchanged)
// ---------------------------------------------------------------------------
__global__ void attn_kernel(const float* __restrict__ out1,
                            const float* __restrict__ lin_w,
                            const float* __restrict__ lin_b,
                            float* __restrict__ attn)
{
    const int b = blockIdx.x, tid = threadIdx.x;
    const float* xb = out1 + (size_t)b * CIN * PP;
    float logit[16], lmax = -1e30f;
#pragma unroll
    for (int i = 0; i < 16; i++) {
        const int p = tid + i * 256;
        float acc = lin_b[p];
        const float4* wr = (const float4*)(lin_w + (size_t)p * CIN);
#pragma unroll
        for (int c4 = 0; c4 < CIN / 4; c4++) {
            float4 w4 = wr[c4];
            acc = fmaf(w4.x, xb[(c4*4+0)*PP + p], acc);
            acc = fmaf(w4.y, xb[(c4*4+1)*PP + p], acc);
            acc = fmaf(w4.z, xb[(c4*4+2)*PP + p], acc);
            acc = fmaf(w4.w, xb[(c4*4+3)*PP + p], acc);
        }
        logit[i] = acc; lmax = fmaxf(lmax, acc);
    }
    __shared__ float red[256];
    red[tid] = lmax; __syncthreads();
    for (int s = 128; s > 0; s >>= 1) { if (tid < s) red[tid] = fmaxf(red[tid], red[tid+s]); __syncthreads(); }
    const float m = red[0]; __syncthreads();
    float lsum = 0.f;
#pragma unroll
    for (int i = 0; i < 16; i++) { logit[i] = expf(logit[i] - m); lsum += logit[i]; }
    red[tid] = lsum; __syncthreads();
    for (int s = 128; s > 0; s >>= 1) { if (tid < s) red[tid] += red[tid+s]; __syncthreads(); }
    const float inv = 1.0f / red[0];
#pragma unroll
    for (int i = 0; i < 16; i++) attn[(size_t)b * PP + tid + i*256] = logit[i] * inv;
}

// ---------------------------------------------------------------------------
__global__ void bo3_kernel(const float* __restrict__ prev,
                           const float* __restrict__ attn,
                           float* __restrict__ out)
{
    const int idx = blockIdx.x * 256 + threadIdx.x;
    const int ox = idx & 31, oy = (idx >> 5) & 31, bc = idx >> 10;
    const int b = bc >> 7;
    const float* pv = prev + (size_t)bc * PP;
    const float* at = attn + (size_t)b * PP;
    const float BIN = 63.0f / 32.0f;
    float acc = 0.f;
#pragma unroll
    for (int sy = 0; sy < 2; sy++) {
        const float ys = ((float)oy + 0.25f + 0.5f * sy) * BIN;
        const int y0 = (int)ys, y1 = min(y0 + 1, HH - 1);
        const float ly = ys - (float)y0, hy = 1.f - ly;
#pragma unroll
        for (int sx = 0; sx < 2; sx++) {
            const float xs = ((float)ox + 0.25f + 0.5f * sx) * BIN;
            const int x0 = (int)xs, x1 = min(x0 + 1, WW - 1);
            const float lx = xs - (float)x0, hx = 1.f - lx;
            const float f00 = pv[y0*WW+x0]*at[y0*WW+x0], f01 = pv[y0*WW+x1]*at[y0*WW+x1];
            const float f10 = pv[y1*WW+x0]*at[y1*WW+x0], f11 = pv[y1*WW+x1]*at[y1*WW+x1];
            acc += hy * (hx*f00 + lx*f01) + ly * (hx*f10 + lx*f11);
        }
    }
    out[idx] = acc * 0.25f;
}

__global__ void combine_kernel(const float* __restrict__ l2,
                               const float* __restrict__ aux,
                               float* __restrict__ out)
{
    const int idx = blockIdx.x * 256 + threadIdx.x;
    const int ox = idx & 31, oy = (idx >> 5) & 31, bc = idx >> 10;
    const float* src = l2 + (size_t)bc * PP;
    const float BIN = 63.0f / 32.0f;
    float acc = 0.f;
#pragma unroll
    for (int sy = 0; sy < 2; sy++) {
        const float ys = ((float)oy + 0.25f + 0.5f * sy) * BIN;
        const int y0 = (int)ys, y1 = min(y0 + 1, HH - 1);
        const float ly = ys - (float)y0, hy = 1.f - ly;
#pragma unroll
        for (int sx = 0; sx < 2; sx++) {
            const float xs = ((float)ox + 0.25f + 0.5f * sx) * BIN;
            const int x0 = (int)xs, x1 = min(x0 + 1, WW - 1);
            const float lx = xs - (float)x0, hx = 1.f - lx;
            acc += hy * (hx*src[y0*WW+x0] + lx*src[y0*WW+x1])
                 + ly * (hx*src[y1*WW+x0] + lx*src[y1*WW+x1]);
        }
    }
    out[idx] = acc * 0.25f + aux[idx] + out[SLICE + idx] + out[2*SLICE + idx];
}

// ---------------------------------------------------------------------------
extern "C" void kernel_launch(void* const* d_in, const int* in_sizes, int n_in,
                              void* d_out, int out_size)
{
    const float* out1   = (const float*)d_in[0];
    const float* out2   = (const float*)d_in[1];
    const float* out3   = (const float*)d_in[2];
    const float* w1     = (const float*)d_in[3];
    const float* b1     = (const float*)d_in[4];
    const float* w2     = (const float*)d_in[5];
    const float* b2     = (const float*)d_in[6];
    const float* w3     = (const float*)d_in[7];
    const float* b3     = (const float*)d_in[8];
    const float* w_aux  = (const float*)d_in[9];
    const float* b_aux  = (const float*)d_in[10];
    const float* w_b2   = (const float*)d_in[11];
    const float* b_b2   = (const float*)d_in[12];
    const float* w_prev = (const float*)d_in[13];
    const float* b_prev = (const float*)d_in[14];
    const float* lin_w  = (const float*)d_in[15];
    const float* lin_b  = (const float*)d_in[16];
    float* out = (float*)d_out;

    float *l2, *prev, *aux, *attn;
    cudaGetSymbolAddress((void**)&l2,   g_l2);
    cudaGetSymbolAddress((void**)&prev, g_prev);
    cudaGetSymbolAddress((void**)&aux,  g_aux);
    cudaGetSymbolAddress((void**)&attn, g_attn);
    ush *x1h,*x1l,*x2h,*x2l,*x3h,*x3l,*x4h,*x4l,*xph,*xpl;
    ush *w1h,*w1l,*w2h,*w2l,*w3h,*w3l,*wph,*wpl,*wbh,*wbl,*wah,*wal;
    cudaGetSymbolAddress((void**)&x1h, g_x1h); cudaGetSymbolAddress((void**)&x1l, g_x1l);
    cudaGetSymbolAddress((void**)&x2h, g_x2h); cudaGetSymbolAddress((void**)&x2l, g_x2l);
    cudaGetSymbolAddress((void**)&x3h, g_x3h); cudaGetSymbolAddress((void**)&x3l, g_x3l);
    cudaGetSymbolAddress((void**)&x4h, g_x4h); cudaGetSymbolAddress((void**)&x4l, g_x4l);
    cudaGetSymbolAddress((void**)&xph, g_xph); cudaGetSymbolAddress((void**)&xpl, g_xpl);
    cudaGetSymbolAddress((void**)&w1h, g_w1h); cudaGetSymbolAddress((void**)&w1l, g_w1l);
    cudaGetSymbolAddress((void**)&w2h, g_w2h); cudaGetSymbolAddress((void**)&w2l, g_w2l);
    cudaGetSymbolAddress((void**)&w3h, g_w3h); cudaGetSymbolAddress((void**)&w3l, g_w3l);
    cudaGetSymbolAddress((void**)&wph, g_wph); cudaGetSymbolAddress((void**)&wpl, g_wpl);
    cudaGetSymbolAddress((void**)&wbh, g_wbh); cudaGetSymbolAddress((void**)&wbl, g_wbl);
    cudaGetSymbolAddress((void**)&wah, g_wah); cudaGetSymbolAddress((void**)&wal, g_wal);

    static cudaStream_t sB = nullptr, sC = nullptr;
    static cudaEvent_t eFork = nullptr, eL2 = nullptr, eB = nullptr, eC = nullptr, eW = nullptr;
    if (!sB) {
        cudaStreamCreateWithFlags(&sB, cudaStreamNonBlocking);
        cudaStreamCreateWithFlags(&sC, cudaStreamNonBlocking);
        cudaEventCreateWithFlags(&eFork, cudaEventDisableTiming);
        cudaEventCreateWithFlags(&eL2,   cudaEventDisableTiming);
        cudaEventCreateWithFlags(&eB,    cudaEventDisableTiming);
        cudaEventCreateWithFlags(&eC,    cudaEventDisableTiming);
        cudaEventCreateWithFlags(&eW,    cudaEventDisableTiming);
    }

    // dynamic smem
    const int smem_m1 = 2 * (264 * 128) + 2 * 16384 + 512;   // slab 67584 + W 32768 + 512
    const int smem_s2 = 2 * (9 * 68 * 32) + 16384 + 512;     // 56064
    cudaFuncSetAttribute(mconv1<1>, cudaFuncAttributeMaxDynamicSharedMemorySize, smem_m1);
    cudaFuncSetAttribute(mconv1<2>, cudaFuncAttributeMaxDynamicSharedMemorySize, smem_m1);
    cudaFuncSetAttribute(mconv<2,2>, cudaFuncAttributeMaxDynamicSharedMemorySize, smem_s2);
    cudaFuncSetAttribute(mconv<4,2>, cudaFuncAttributeMaxDynamicSharedMemorySize, smem_s2);

    const dim3 gsM1(32, 1, 32);      // stride-1 tensor convs
    const dim3 gsM2(8, 1, 32);       // stride-2 tensor convs
    const dim3 gsA(64, 32);          // asplit
    const int  nPix = (int)(SLICE / 256);

    cudaEventRecord(eFork, 0);
    cudaStreamWaitEvent(sB, eFork, 0);
    cudaStreamWaitEvent(sC, eFork, 0);

    // ---- stream B: attn + prev chain + bo3 ----
    attn_kernel<<<BB, 256, 0, sB>>>(out1, lin_w, lin_b, attn);
    wsplit<<<(128*128*9 + 255)/256, 256, 0, sB>>>(w_prev, 128, wph, wpl);
    asplit<128><<<gsA, 256, 0, sB>>>(out2, out3, 64, xph, xpl);
    mconv1<2><<<gsM1, 256, smem_m1, sB>>>(xph, xpl, xph, xpl, 2, wph, wpl, b_prev,
                                          prev, nullptr, nullptr);
    bo3_kernel<<<nPix, 256, 0, sB>>>(prev, attn, out + 2*SLICE);
    cudaEventRecord(eB, sB);

    // ---- stream C: weight preps off critical path ----
    wsplit<<<(128*128*9 + 255)/256, 256, 0, sC>>>(w2, 128, w2h, w2l);
    wsplit<<<(128*128*9 + 255)/256, 256, 0, sC>>>(w3, 128, w3h, w3l);
    wsplit<<<(128*128*9 + 255)/256, 256, 0, sC>>>(w_aux, 128, wah, wal);
    wsplit<<<(128*256*9 + 255)/256, 256, 0, sC>>>(w_b2, 256, wbh, wbl);
    cudaEventRecord(eW, sC);

    // ---- main chain ----
    wsplit<<<(128*64*9 + 255)/256, 256>>>(w1, 64, w1h, w1l);
    asplit<64><<<gsA, 256>>>(out1, nullptr, 64, x1h, x1l);
    mconv1<1><<<gsM1, 256, smem_m1>>>(x1h, x1l, x1h, x1l, 1, w1h, w1l, b1,
                                      nullptr, x2h, x2l);               // l1 (HWC only)
    cudaStreamWaitEvent(0, eW, 0);
    mconv1<2><<<gsM1, 256, smem_m1>>>(x2h, x2l, x2h, x2l, 2, w2h, w2l, b2,
                                      l2, x3h, x3l);                    // l2

    cudaEventRecord(eL2, 0);
    cudaStreamWaitEvent(sC, eL2, 0);
    mconv<4,2><<<gsM2, 256, smem_s2, sC>>>(x2h, x2l, x3h, x3l, 2, wbh, wbl, b_b2,
                                           out + SLICE, nullptr, nullptr);  // block_out2
    cudaEventRecord(eC, sC);

    mconv1<2><<<gsM1, 256, smem_m1>>>(x3h, x3l, x3h, x3l, 2, w3h, w3l, b3,
                                      nullptr, x4h, x4l);               // l3 (HWC only)
    mconv<2,2><<<gsM2, 256, smem_s2>>>(x4h, x4l, x4h, x4l, 2, wah, wal, b_aux,
                                       aux, nullptr, nullptr);          // aux

    cudaStreamWaitEvent(0, eB, 0);
    cudaStreamWaitEvent(0, eC, 0);
    combine_kernel<<<nPix, 256>>>(l2, aux, out);
}